// round 9
// baseline (speedup 1.0000x reference)
#include <cuda_runtime.h>
#include <stdint.h>

#define D 128
#define DV 32              // float4 chunks per row
#define MAXN 50048
#define MAXE 1600000

// Zero-initialized at module load. Invariant: g_deg and g_cnt are all-zero at
// entry to kernel_launch, and every call restores that before it returns
// (k_scan_dis zeroes deg; the final k_agg zeroes cnt).
__device__ int      g_deg[MAXN];
__device__ int      g_cnt[MAXN];
__device__ int2     g_adj[MAXE];        // dst-sorted: {src, bits(dis[src])}
__device__ int      g_start[MAXN + 1];  // CSR offsets by dst
__device__ float    g_dis[MAXN];
__device__ float    g_t[MAXN * D];      // GEMM output (pre-aggregation)
__device__ float    g_h[MAXN * D];      // hidden after layer 1
__device__ unsigned g_w1p[D * D];       // W1, tf32 bits, fragment-packed
__device__ unsigned g_w2p[D * D];       // W2, tf32 bits, fragment-packed

__device__ __forceinline__ unsigned f2tf32(float f) {
    unsigned u;
    asm("cvt.rna.tf32.f32 %0, %1;" : "=r"(u) : "f"(f));
    return u;
}

// Fragment-packed W layout: word i <-> (kk4, wn, g, t, ks, nt, b):
//   w    = i & 31; ks = w >> 3; nt = (w >> 1) & 3; b = w & 1;
//   t    = (i >> 5) & 3;  g = (i >> 7) & 7;  wn = (i >> 10) & 3;  kk4 = i >> 12;
//   k    = kk4*32 + ks*8 + t + b*4;  n = wn*32 + nt*8 + g;
//   Wp[i] = tf32(W[k*D + n])
// Each thread (wn,g,t) reads its 32 words for slab kk4 as 8 contiguous uint4.
__device__ __forceinline__ void pack_w(unsigned* dst, const float* __restrict__ W, int i) {
    int w_  = i & 31;
    int ks  = w_ >> 3;
    int nt  = (w_ >> 1) & 3;
    int b   = w_ & 1;
    int t   = (i >> 5) & 3;
    int g   = (i >> 7) & 7;
    int wn  = (i >> 10) & 3;
    int kk4 = i >> 12;
    int k = kk4 * 32 + ks * 8 + t + b * 4;
    int n = wn * 32 + nt * 8 + g;
    dst[i] = f2tf32(W[k * D + n]);
}

// ---------------------------------------------------------------------------
// Per-block dtype detect: int64 little-endian values < 2^32 -> odd 32-bit
// words all zero over 128 samples.
// ---------------------------------------------------------------------------
__device__ __forceinline__ int detect_is64(const unsigned* p, int* s_flag) {
    if (threadIdx.x == 0) *s_flag = 0;
    __syncthreads();
    if (threadIdx.x < 64) {
        unsigned nz = p[2 * threadIdx.x + 1] | p[2 * threadIdx.x + 129];
        if (nz) atomicOr(s_flag, 1);
    }
    __syncthreads();
    return *s_flag ? 0 : 1;
}

// Parse edges (either dtype) and count degrees. First 128 blocks also pack
// the weight matrices into tf32 fragment order.
__global__ void k_prep(const void* p, int E,
                       const float* __restrict__ W1, const float* __restrict__ W2) {
    __shared__ int s_flag;
    int is64 = detect_is64((const unsigned*)p, &s_flag);
    int gt = blockIdx.x * blockDim.x + threadIdx.x;
    if (gt < D * D)          pack_w(g_w1p, W1, gt);
    else if (gt < 2 * D * D) pack_w(g_w2p, W2, gt - D * D);
    int e = gt;
    if (e >= E) return;
    int r, c;
    if (is64) {
        const long long* q = (const long long*)p;
        r = (int)q[e];
        c = (int)q[(long long)E + e];
    } else {
        const int* q = (const int*)p;
        r = q[e];
        c = q[E + e];
    }
    atomicAdd(&g_deg[r], 1);
    atomicAdd(&g_cnt[c], 1);
}

// Single block: exclusive scan g_cnt -> g_start, zero cursors,
// dis = rsqrt(deg+1) (self loop), re-zero g_deg (invariant restore).
__global__ void k_scan_dis(int N, int E) {
    __shared__ int sh[1024];
    const int tid = threadIdx.x;
    const int per = (N + 1023) >> 10;
    const int base = tid * per;
    int s = 0;
    for (int i = 0; i < per; i++) {
        int idx = base + i;
        if (idx < N) s += g_cnt[idx];
    }
    sh[tid] = s;
    __syncthreads();
    for (int off = 1; off < 1024; off <<= 1) {
        int t = (tid >= off) ? sh[tid - off] : 0;
        __syncthreads();
        sh[tid] += t;
        __syncthreads();
    }
    int run = sh[tid] - s;
    for (int i = 0; i < per; i++) {
        int idx = base + i;
        if (idx < N) {
            int c = g_cnt[idx];
            g_start[idx] = run;
            run += c;
            g_cnt[idx] = 0;
            g_dis[idx] = rsqrtf((float)(g_deg[idx] + 1));
            g_deg[idx] = 0;
        }
    }
    if (tid == 0) g_start[N] = E;
}

__global__ void k_scatter(const void* p, int E) {
    __shared__ int s_flag;
    int is64 = detect_is64((const unsigned*)p, &s_flag);
    int e = blockIdx.x * blockDim.x + threadIdx.x;
    if (e >= E) return;
    int r, c;
    if (is64) {
        const long long* q = (const long long*)p;
        r = (int)q[e];
        c = (int)q[(long long)E + e];
    } else {
        const int* q = (const int*)p;
        r = q[e];
        c = q[E + e];
    }
    int pos = g_start[c] + atomicAdd(&g_cnt[c], 1);
    g_adj[pos] = make_int2(r, __float_as_int(g_dis[r]));
}

// ---------------------------------------------------------------------------
// GEMM (tf32 tensor cores): C[N,128] = A[N,128] @ W[128,128]  (no bias).
// BM=64, BN=128: 8 warps (2m x 4n), warp tile 32x32, 3 blocks/SM.
// A staged in smem with permuted k-order [0,4,1,5,2,6,3,7] per 8-group ->
// fragment pairs (k=t, k=t+4) adjacent -> LDS.64; row stride 40 words ->
// banks (8g+2t)%32 distinct per phase. W read as 8x LDG.128 per slab from
// the fragment-packed layout (L1-resident).
// ---------------------------------------------------------------------------
__global__ void __launch_bounds__(256, 3)
k_gemm_tf32(const float* __restrict__ A, const unsigned* __restrict__ Wp,
            float* __restrict__ C, int N) {
    __shared__ unsigned As[64][40];

    const int tid  = threadIdx.x;
    const int wid  = tid >> 5;
    const int lane = tid & 31;
    const int g    = lane >> 2;     // groupID
    const int t    = lane & 3;      // threadID_in_group
    const int wm   = wid >> 2;      // 0..1  -> 32-row half
    const int wn   = wid & 3;       // 0..3  -> 32-col quarter
    const int row0 = blockIdx.x * 64;

    float acc[2][4][4];
    #pragma unroll
    for (int mt = 0; mt < 2; mt++)
        #pragma unroll
        for (int nt = 0; nt < 4; nt++)
            #pragma unroll
            for (int c = 0; c < 4; c++) acc[mt][nt][c] = 0.f;

    // Per-thread W fragment base for slab kk4: (((kk4*4+wn)*8+g)*4+t)*32 words
    const unsigned wbase0 = (((unsigned)wn * 8 + g) * 4 + t) * 32;

    for (int kk4 = 0; kk4 < 4; kk4++) {
        const int kk = kk4 * 32;
        // Stage A slab: 64 rows x 32 k, permuted k-order, tf32 bits.
        #pragma unroll
        for (int it = 0; it < 2; it++) {
            int idx = tid + it * 256;
            int m  = idx >> 3;        // 0..63
            int k4 = idx & 7;         // 0..7 (float4 index)
            float4 v = make_float4(0.f, 0.f, 0.f, 0.f);
            int gr = row0 + m;
            if (gr < N) v = *(const float4*)(A + (long)gr * D + kk + k4 * 4);
            float vv[4] = {v.x, v.y, v.z, v.w};
            #pragma unroll
            for (int j = 0; j < 4; j++) {
                int l = k4 * 4 + j;                      // local k 0..31
                int pos = (l >> 3) * 8 + ((l & 3) * 2 + ((l >> 2) & 1));
                As[m][pos] = f2tf32(vv[j]);
            }
        }
        __syncthreads();

        // W fragments for this slab: 8 contiguous uint4 per thread.
        const uint4* wq = (const uint4*)(Wp + (kk4 * 4096 + wbase0));
        #pragma unroll
        for (int ks = 0; ks < 4; ks++) {
            uint4 u0 = __ldg(&wq[ks * 2]);       // nt0:{b0,b1}, nt1:{b0,b1}
            uint4 u1 = __ldg(&wq[ks * 2 + 1]);   // nt2:{b0,b1}, nt3:{b0,b1}
            unsigned bf[4][2] = {{u0.x, u0.y}, {u0.z, u0.w},
                                 {u1.x, u1.y}, {u1.z, u1.w}};
            #pragma unroll
            for (int mt = 0; mt < 2; mt++) {
                int mb = wm * 32 + mt * 16;
                uint2 ra = *(const uint2*)&As[mb + g    ][ks * 8 + 2 * t]; // a0,a2
                uint2 rb = *(const uint2*)&As[mb + g + 8][ks * 8 + 2 * t]; // a1,a3
                #pragma unroll
                for (int nt = 0; nt < 4; nt++) {
                    asm volatile(
                        "mma.sync.aligned.m16n8k8.row.col.f32.tf32.tf32.f32 "
                        "{%0,%1,%2,%3}, {%4,%5,%6,%7}, {%8,%9}, {%0,%1,%2,%3};"
                        : "+f"(acc[mt][nt][0]), "+f"(acc[mt][nt][1]),
                          "+f"(acc[mt][nt][2]), "+f"(acc[mt][nt][3])
                        : "r"(ra.x), "r"(rb.x), "r"(ra.y), "r"(rb.y),
                          "r"(bf[nt][0]), "r"(bf[nt][1]));
                }
            }
        }
        __syncthreads();
    }

    // Epilogue: c0=[g][2t], c1=[g][2t+1], c2=[g+8][2t], c3=[g+8][2t+1]
    #pragma unroll
    for (int mt = 0; mt < 2; mt++) {
        int r0 = row0 + wm * 32 + mt * 16 + g;
        int r1 = r0 + 8;
        #pragma unroll
        for (int nt = 0; nt < 4; nt++) {
            int n = wn * 32 + nt * 8 + 2 * t;
            if (r0 < N)
                *(float2*)(C + (long)r0 * D + n) = make_float2(acc[mt][nt][0], acc[mt][nt][1]);
            if (r1 < N)
                *(float2*)(C + (long)r1 * D + n) = make_float2(acc[mt][nt][2], acc[mt][nt][3]);
        }
    }
}

// ---------------------------------------------------------------------------
// Aggregation (+ bias, optional ReLU): one warp per dst node, fp32 gather,
// 4 loads in flight, 2 accumulators (regs=32, occ 82%, measured 52us).
// out = dis[n]*(sum_e dis[src]*t[src]) + dis[n]^2 * t[n] + bias
// ---------------------------------------------------------------------------
template <bool RELU, bool CLEAN>
__global__ void __launch_bounds__(256)
k_agg(const float4* __restrict__ src, const float4* __restrict__ bias4,
      float4* __restrict__ dst, int N) {
    if (CLEAN) {
        int idx = blockIdx.x * blockDim.x + threadIdx.x;
        if (idx < MAXN) g_cnt[idx] = 0;   // restore invariant
    }
    int w = (blockIdx.x * blockDim.x + threadIdx.x) >> 5;
    if (w >= N) return;
    const int lane = threadIdx.x & 31;
    int i = g_start[w];
    const int end = g_start[w + 1];

    float4 a0 = make_float4(0.f, 0.f, 0.f, 0.f);
    float4 a1 = make_float4(0.f, 0.f, 0.f, 0.f);

    for (; i + 4 <= end; i += 4) {
        int2 e0 = __ldg(&g_adj[i]);
        int2 e1 = __ldg(&g_adj[i + 1]);
        int2 e2 = __ldg(&g_adj[i + 2]);
        int2 e3 = __ldg(&g_adj[i + 3]);
        float4 v0 = __ldg(&src[(long)e0.x * DV + lane]);
        float4 v1 = __ldg(&src[(long)e1.x * DV + lane]);
        float4 v2 = __ldg(&src[(long)e2.x * DV + lane]);
        float4 v3 = __ldg(&src[(long)e3.x * DV + lane]);
        float w0 = __int_as_float(e0.y);
        float w1 = __int_as_float(e1.y);
        float w2 = __int_as_float(e2.y);
        float w3 = __int_as_float(e3.y);
        a0.x += w0 * v0.x; a0.y += w0 * v0.y; a0.z += w0 * v0.z; a0.w += w0 * v0.w;
        a1.x += w1 * v1.x; a1.y += w1 * v1.y; a1.z += w1 * v1.z; a1.w += w1 * v1.w;
        a0.x += w2 * v2.x; a0.y += w2 * v2.y; a0.z += w2 * v2.z; a0.w += w2 * v2.w;
        a1.x += w3 * v3.x; a1.y += w3 * v3.y; a1.z += w3 * v3.z; a1.w += w3 * v3.w;
    }
    for (; i < end; i++) {
        int2 e0 = __ldg(&g_adj[i]);
        float4 v0 = __ldg(&src[(long)e0.x * DV + lane]);
        float w0 = __int_as_float(e0.y);
        a0.x += w0 * v0.x; a0.y += w0 * v0.y; a0.z += w0 * v0.z; a0.w += w0 * v0.w;
    }

    float di = g_dis[w];
    float sw = di * di;
    float4 sv = __ldg(&src[(long)w * DV + lane]);
    float4 bv = __ldg(&bias4[lane]);
    float4 o;
    o.x = di * (a0.x + a1.x) + sw * sv.x + bv.x;
    o.y = di * (a0.y + a1.y) + sw * sv.y + bv.y;
    o.z = di * (a0.z + a1.z) + sw * sv.z + bv.z;
    o.w = di * (a0.w + a1.w) + sw * sv.w + bv.w;
    if (RELU) {
        o.x = fmaxf(o.x, 0.f); o.y = fmaxf(o.y, 0.f);
        o.z = fmaxf(o.z, 0.f); o.w = fmaxf(o.w, 0.f);
    }
    dst[(long)w * DV + lane] = o;
}

extern "C" void kernel_launch(void* const* d_in, const int* in_sizes, int n_in,
                              void* d_out, int out_size) {
    const float* x  = (const float*)d_in[0];
    const void*  ei = d_in[1];
    const float* W1 = (const float*)d_in[2];
    const float* b1 = (const float*)d_in[3];
    const float* W2 = (const float*)d_in[4];
    const float* b2 = (const float*)d_in[5];
    float* out = (float*)d_out;

    const int N = in_sizes[0] / D;
    const int E = in_sizes[1] / 2;

    float*    t_ptr = nullptr;
    float*    h_ptr = nullptr;
    unsigned* w1p   = nullptr;
    unsigned* w2p   = nullptr;
    cudaGetSymbolAddress((void**)&t_ptr, g_t);
    cudaGetSymbolAddress((void**)&h_ptr, g_h);
    cudaGetSymbolAddress((void**)&w1p,   g_w1p);
    cudaGetSymbolAddress((void**)&w2p,   g_w2p);

    const int T = 256;
    const int eGrid    = (E + T - 1) / T;
    const int aggGrid  = (N * 32 + T - 1) / T;
    const int gemmGrid = (N + 63) / 64;

    // Uses GEMM/Agg commutativity: Agg(x)@W = Agg(x@W); bias+ReLU fold into
    // the agg epilogue. GEMM1 is launch #4 (ncu sample slot).
    k_prep<<<eGrid, T>>>(ei, E, W1, W2);                                  // 1
    k_scan_dis<<<1, 1024>>>(N, E);                                        // 2
    k_scatter<<<eGrid, T>>>(ei, E);                                       // 3
    k_gemm_tf32<<<gemmGrid, T>>>(x, w1p, t_ptr, N);                       // 4
    k_agg<true, false><<<aggGrid, T>>>((const float4*)t_ptr,              // 5
                                       (const float4*)b1, (float4*)h_ptr, N);
    k_gemm_tf32<<<gemmGrid, T>>>(h_ptr, w2p, t_ptr, N);                   // 6
    k_agg<false, true><<<aggGrid, T>>>((const float4*)t_ptr,              // 7
                                       (const float4*)b2, (float4*)out, N);
}

// round 10
// speedup vs baseline: 1.1453x; 1.1453x over previous
#include <cuda_runtime.h>
#include <stdint.h>

#define D 128
#define DV 32              // float4 chunks per row
#define MAXN 50048
#define MAXE 1600000

// Zero-initialized at module load. Invariant: g_deg and g_cnt are all-zero at
// entry to kernel_launch, and every call restores that before it returns
// (k_scan_dis zeroes deg; the final k_agg zeroes cnt).
__device__ int      g_deg[MAXN];
__device__ int      g_cnt[MAXN];
__device__ int2     g_adj[MAXE];        // dst-sorted: {src, bits(dis[src])}
__device__ int      g_start[MAXN + 1];  // CSR offsets by dst
__device__ float    g_dis[MAXN];
__device__ float    g_t[MAXN * D];      // GEMM output (pre-aggregation)
__device__ float    g_h[MAXN * D];      // hidden after layer 1
__device__ unsigned g_w1p[D * D];       // W1, tf32 bits, lane-major fragment pack
__device__ unsigned g_w2p[D * D];       // W2, tf32 bits, lane-major fragment pack

__device__ __forceinline__ unsigned f2tf32(float f) {
    unsigned u;
    asm("cvt.rna.tf32.f32 %0, %1;" : "=r"(u) : "f"(f));
    return u;
}

// Lane-major fragment pack:
//   word i = (((kk4*4 + wn)*4 + ks)*2 + jj)*128 + lane*4 + c
//   j = jj*4 + c; nt = j>>1; b = j&1; t = lane&3; g = lane>>2
//   k = kk4*32 + ks*8 + t + b*4;  n = wn*32 + nt*8 + g
// Consumer: per (warp wn, slab kk4, step ks) each lane reads 2 uint4 at
// lane*16B offsets -> warp-wide LDG.128 covers 512 contiguous bytes.
__device__ __forceinline__ void pack_w(unsigned* dst, const float* __restrict__ W, int i) {
    int c    = i & 3;
    int lane = (i >> 2) & 31;
    int jj   = (i >> 7) & 1;
    int ks   = (i >> 8) & 3;
    int wn   = (i >> 10) & 3;
    int kk4  = i >> 12;
    int j  = jj * 4 + c;
    int nt = j >> 1;
    int b  = j & 1;
    int t  = lane & 3;
    int g  = lane >> 2;
    int k = kk4 * 32 + ks * 8 + t + b * 4;
    int n = wn * 32 + nt * 8 + g;
    dst[i] = f2tf32(W[k * D + n]);
}

// ---------------------------------------------------------------------------
// Per-block dtype detect: int64 little-endian values < 2^32 -> odd 32-bit
// words all zero over 128 samples.
// ---------------------------------------------------------------------------
__device__ __forceinline__ int detect_is64(const unsigned* p, int* s_flag) {
    if (threadIdx.x == 0) *s_flag = 0;
    __syncthreads();
    if (threadIdx.x < 64) {
        unsigned nz = p[2 * threadIdx.x + 1] | p[2 * threadIdx.x + 129];
        if (nz) atomicOr(s_flag, 1);
    }
    __syncthreads();
    return *s_flag ? 0 : 1;
}

// Parse edges (either dtype) and count degrees. First 128 blocks also pack
// the weight matrices.
__global__ void k_prep(const void* p, int E,
                       const float* __restrict__ W1, const float* __restrict__ W2) {
    __shared__ int s_flag;
    int is64 = detect_is64((const unsigned*)p, &s_flag);
    int gt = blockIdx.x * blockDim.x + threadIdx.x;
    if (gt < D * D)          pack_w(g_w1p, W1, gt);
    else if (gt < 2 * D * D) pack_w(g_w2p, W2, gt - D * D);
    int e = gt;
    if (e >= E) return;
    int r, c;
    if (is64) {
        const long long* q = (const long long*)p;
        r = (int)q[e];
        c = (int)q[(long long)E + e];
    } else {
        const int* q = (const int*)p;
        r = q[e];
        c = q[E + e];
    }
    atomicAdd(&g_deg[r], 1);
    atomicAdd(&g_cnt[c], 1);
}

// Single block: exclusive scan g_cnt -> g_start, zero cursors,
// dis = rsqrt(deg+1) (self loop), re-zero g_deg (invariant restore).
__global__ void k_scan_dis(int N, int E) {
    __shared__ int sh[1024];
    const int tid = threadIdx.x;
    const int per = (N + 1023) >> 10;
    const int base = tid * per;
    int s = 0;
    for (int i = 0; i < per; i++) {
        int idx = base + i;
        if (idx < N) s += g_cnt[idx];
    }
    sh[tid] = s;
    __syncthreads();
    for (int off = 1; off < 1024; off <<= 1) {
        int t = (tid >= off) ? sh[tid - off] : 0;
        __syncthreads();
        sh[tid] += t;
        __syncthreads();
    }
    int run = sh[tid] - s;
    for (int i = 0; i < per; i++) {
        int idx = base + i;
        if (idx < N) {
            int c = g_cnt[idx];
            g_start[idx] = run;
            run += c;
            g_cnt[idx] = 0;
            g_dis[idx] = rsqrtf((float)(g_deg[idx] + 1));
            g_deg[idx] = 0;
        }
    }
    if (tid == 0) g_start[N] = E;
}

// ---------------------------------------------------------------------------
// FUSED: blocks [0, gemmBlocks) run GEMM-1 (tf32, x @ W1 -> g_t);
//        blocks [gemmBlocks, ...) scatter edges into the dst-sorted adjacency.
// The two sides are independent (scatter needs g_start/g_dis; GEMM needs x/W1)
// and stress disjoint pipes (tensor+LDS vs L2 atomics) -> overlap.
//
// GEMM: BM=64, BN=128, 8 warps (2m x 4n), warp tile 32x32, round-8 A staging
// (As[64][36], contiguous STS; LDS.32 fragments, conflict-free), W via
// 2x LDG.128 per slab from the lane-major pack.
// ---------------------------------------------------------------------------
__global__ void __launch_bounds__(256, 3)
k_gemm_scatter(const float* __restrict__ A, const unsigned* __restrict__ Wp,
               float* __restrict__ C, int N,
               const void* p, int E, int gemmBlocks) {
    __shared__ unsigned As[64][36];

    if (blockIdx.x >= gemmBlocks) {
        // ---------------- scatter branch ----------------
        int is64 = detect_is64((const unsigned*)p, (int*)&As[0][0]);
        int e = (blockIdx.x - gemmBlocks) * blockDim.x + threadIdx.x;
        if (e >= E) return;
        int r, c;
        if (is64) {
            const long long* q = (const long long*)p;
            r = (int)q[e];
            c = (int)q[(long long)E + e];
        } else {
            const int* q = (const int*)p;
            r = q[e];
            c = q[E + e];
        }
        int pos = g_start[c] + atomicAdd(&g_cnt[c], 1);
        g_adj[pos] = make_int2(r, __float_as_int(g_dis[r]));
        return;
    }

    // ---------------- GEMM branch ----------------
    const int tid  = threadIdx.x;
    const int wid  = tid >> 5;
    const int lane = tid & 31;
    const int g    = lane >> 2;     // groupID
    const int t    = lane & 3;      // threadID_in_group
    const int wm   = wid >> 2;      // 0..1  -> 32-row half
    const int wn   = wid & 3;       // 0..3  -> 32-col quarter
    const int row0 = blockIdx.x * 64;

    float acc[2][4][4];
    #pragma unroll
    for (int mt = 0; mt < 2; mt++)
        #pragma unroll
        for (int nt = 0; nt < 4; nt++)
            #pragma unroll
            for (int c = 0; c < 4; c++) acc[mt][nt][c] = 0.f;

    for (int kk4 = 0; kk4 < 4; kk4++) {
        const int kk = kk4 * 32;
        // Stage A slab: 64 rows x 32 k (contiguous store, round-8 proven).
        #pragma unroll
        for (int it = 0; it < 2; it++) {
            int idx = tid + it * 256;
            int m  = idx >> 3;        // 0..63
            int k4 = idx & 7;         // 0..7
            float4 v = make_float4(0.f, 0.f, 0.f, 0.f);
            int gr = row0 + m;
            if (gr < N) v = *(const float4*)(A + (long)gr * D + kk + k4 * 4);
            As[m][k4 * 4 + 0] = f2tf32(v.x);
            As[m][k4 * 4 + 1] = f2tf32(v.y);
            As[m][k4 * 4 + 2] = f2tf32(v.z);
            As[m][k4 * 4 + 3] = f2tf32(v.w);
        }
        __syncthreads();

        // This warp's packed W for the slab: 2 coalesced LDG.128 per ks.
        const unsigned* wsl = Wp + ((kk4 * 4 + wn) * 4) * 256 + lane * 4;
        #pragma unroll
        for (int ks = 0; ks < 4; ks++) {
            uint4 u0 = __ldg((const uint4*)(wsl + ks * 256));
            uint4 u1 = __ldg((const uint4*)(wsl + ks * 256 + 128));
            unsigned bf[4][2] = {{u0.x, u0.y}, {u0.z, u0.w},
                                 {u1.x, u1.y}, {u1.z, u1.w}};
            #pragma unroll
            for (int mt = 0; mt < 2; mt++) {
                int mb = wm * 32 + mt * 16;
                unsigned a0 = As[mb + g    ][ks * 8 + t    ];
                unsigned a1 = As[mb + g + 8][ks * 8 + t    ];
                unsigned a2 = As[mb + g    ][ks * 8 + t + 4];
                unsigned a3 = As[mb + g + 8][ks * 8 + t + 4];
                #pragma unroll
                for (int nt = 0; nt < 4; nt++) {
                    asm volatile(
                        "mma.sync.aligned.m16n8k8.row.col.f32.tf32.tf32.f32 "
                        "{%0,%1,%2,%3}, {%4,%5,%6,%7}, {%8,%9}, {%0,%1,%2,%3};"
                        : "+f"(acc[mt][nt][0]), "+f"(acc[mt][nt][1]),
                          "+f"(acc[mt][nt][2]), "+f"(acc[mt][nt][3])
                        : "r"(a0), "r"(a1), "r"(a2), "r"(a3),
                          "r"(bf[nt][0]), "r"(bf[nt][1]));
                }
            }
        }
        __syncthreads();
    }

    #pragma unroll
    for (int mt = 0; mt < 2; mt++) {
        int r0 = row0 + wm * 32 + mt * 16 + g;
        int r1 = r0 + 8;
        #pragma unroll
        for (int nt = 0; nt < 4; nt++) {
            int n = wn * 32 + nt * 8 + 2 * t;
            if (r0 < N)
                *(float2*)(C + (long)r0 * D + n) = make_float2(acc[mt][nt][0], acc[mt][nt][1]);
            if (r1 < N)
                *(float2*)(C + (long)r1 * D + n) = make_float2(acc[mt][nt][2], acc[mt][nt][3]);
        }
    }
}

// Standalone GEMM (layer 2), same algorithm as the fused GEMM branch.
__global__ void __launch_bounds__(256, 3)
k_gemm_tf32(const float* __restrict__ A, const unsigned* __restrict__ Wp,
            float* __restrict__ C, int N) {
    __shared__ unsigned As[64][36];

    const int tid  = threadIdx.x;
    const int wid  = tid >> 5;
    const int lane = tid & 31;
    const int g    = lane >> 2;
    const int t    = lane & 3;
    const int wm   = wid >> 2;
    const int wn   = wid & 3;
    const int row0 = blockIdx.x * 64;

    float acc[2][4][4];
    #pragma unroll
    for (int mt = 0; mt < 2; mt++)
        #pragma unroll
        for (int nt = 0; nt < 4; nt++)
            #pragma unroll
            for (int c = 0; c < 4; c++) acc[mt][nt][c] = 0.f;

    for (int kk4 = 0; kk4 < 4; kk4++) {
        const int kk = kk4 * 32;
        #pragma unroll
        for (int it = 0; it < 2; it++) {
            int idx = tid + it * 256;
            int m  = idx >> 3;
            int k4 = idx & 7;
            float4 v = make_float4(0.f, 0.f, 0.f, 0.f);
            int gr = row0 + m;
            if (gr < N) v = *(const float4*)(A + (long)gr * D + kk + k4 * 4);
            As[m][k4 * 4 + 0] = f2tf32(v.x);
            As[m][k4 * 4 + 1] = f2tf32(v.y);
            As[m][k4 * 4 + 2] = f2tf32(v.z);
            As[m][k4 * 4 + 3] = f2tf32(v.w);
        }
        __syncthreads();

        const unsigned* wsl = Wp + ((kk4 * 4 + wn) * 4) * 256 + lane * 4;
        #pragma unroll
        for (int ks = 0; ks < 4; ks++) {
            uint4 u0 = __ldg((const uint4*)(wsl + ks * 256));
            uint4 u1 = __ldg((const uint4*)(wsl + ks * 256 + 128));
            unsigned bf[4][2] = {{u0.x, u0.y}, {u0.z, u0.w},
                                 {u1.x, u1.y}, {u1.z, u1.w}};
            #pragma unroll
            for (int mt = 0; mt < 2; mt++) {
                int mb = wm * 32 + mt * 16;
                unsigned a0 = As[mb + g    ][ks * 8 + t    ];
                unsigned a1 = As[mb + g + 8][ks * 8 + t    ];
                unsigned a2 = As[mb + g    ][ks * 8 + t + 4];
                unsigned a3 = As[mb + g + 8][ks * 8 + t + 4];
                #pragma unroll
                for (int nt = 0; nt < 4; nt++) {
                    asm volatile(
                        "mma.sync.aligned.m16n8k8.row.col.f32.tf32.tf32.f32 "
                        "{%0,%1,%2,%3}, {%4,%5,%6,%7}, {%8,%9}, {%0,%1,%2,%3};"
                        : "+f"(acc[mt][nt][0]), "+f"(acc[mt][nt][1]),
                          "+f"(acc[mt][nt][2]), "+f"(acc[mt][nt][3])
                        : "r"(a0), "r"(a1), "r"(a2), "r"(a3),
                          "r"(bf[nt][0]), "r"(bf[nt][1]));
                }
            }
        }
        __syncthreads();
    }

    #pragma unroll
    for (int mt = 0; mt < 2; mt++) {
        int r0 = row0 + wm * 32 + mt * 16 + g;
        int r1 = r0 + 8;
        #pragma unroll
        for (int nt = 0; nt < 4; nt++) {
            int n = wn * 32 + nt * 8 + 2 * t;
            if (r0 < N)
                *(float2*)(C + (long)r0 * D + n) = make_float2(acc[mt][nt][0], acc[mt][nt][1]);
            if (r1 < N)
                *(float2*)(C + (long)r1 * D + n) = make_float2(acc[mt][nt][2], acc[mt][nt][3]);
        }
    }
}

// ---------------------------------------------------------------------------
// Aggregation (+ bias, optional ReLU): one warp per dst node, fp32 gather,
// 4 loads in flight, 2 accumulators (regs=32, occ 82%, measured 52us).
// out = dis[n]*(sum_e dis[src]*t[src]) + dis[n]^2 * t[n] + bias
// ---------------------------------------------------------------------------
template <bool RELU, bool CLEAN>
__global__ void __launch_bounds__(256)
k_agg(const float4* __restrict__ src, const float4* __restrict__ bias4,
      float4* __restrict__ dst, int N) {
    if (CLEAN) {
        int idx = blockIdx.x * blockDim.x + threadIdx.x;
        if (idx < MAXN) g_cnt[idx] = 0;   // restore invariant
    }
    int w = (blockIdx.x * blockDim.x + threadIdx.x) >> 5;
    if (w >= N) return;
    const int lane = threadIdx.x & 31;
    int i = g_start[w];
    const int end = g_start[w + 1];

    float4 a0 = make_float4(0.f, 0.f, 0.f, 0.f);
    float4 a1 = make_float4(0.f, 0.f, 0.f, 0.f);

    for (; i + 4 <= end; i += 4) {
        int2 e0 = __ldg(&g_adj[i]);
        int2 e1 = __ldg(&g_adj[i + 1]);
        int2 e2 = __ldg(&g_adj[i + 2]);
        int2 e3 = __ldg(&g_adj[i + 3]);
        float4 v0 = __ldg(&src[(long)e0.x * DV + lane]);
        float4 v1 = __ldg(&src[(long)e1.x * DV + lane]);
        float4 v2 = __ldg(&src[(long)e2.x * DV + lane]);
        float4 v3 = __ldg(&src[(long)e3.x * DV + lane]);
        float w0 = __int_as_float(e0.y);
        float w1 = __int_as_float(e1.y);
        float w2 = __int_as_float(e2.y);
        float w3 = __int_as_float(e3.y);
        a0.x += w0 * v0.x; a0.y += w0 * v0.y; a0.z += w0 * v0.z; a0.w += w0 * v0.w;
        a1.x += w1 * v1.x; a1.y += w1 * v1.y; a1.z += w1 * v1.z; a1.w += w1 * v1.w;
        a0.x += w2 * v2.x; a0.y += w2 * v2.y; a0.z += w2 * v2.z; a0.w += w2 * v2.w;
        a1.x += w3 * v3.x; a1.y += w3 * v3.y; a1.z += w3 * v3.z; a1.w += w3 * v3.w;
    }
    for (; i < end; i++) {
        int2 e0 = __ldg(&g_adj[i]);
        float4 v0 = __ldg(&src[(long)e0.x * DV + lane]);
        float w0 = __int_as_float(e0.y);
        a0.x += w0 * v0.x; a0.y += w0 * v0.y; a0.z += w0 * v0.z; a0.w += w0 * v0.w;
    }

    float di = g_dis[w];
    float sw = di * di;
    float4 sv = __ldg(&src[(long)w * DV + lane]);
    float4 bv = __ldg(&bias4[lane]);
    float4 o;
    o.x = di * (a0.x + a1.x) + sw * sv.x + bv.x;
    o.y = di * (a0.y + a1.y) + sw * sv.y + bv.y;
    o.z = di * (a0.z + a1.z) + sw * sv.z + bv.z;
    o.w = di * (a0.w + a1.w) + sw * sv.w + bv.w;
    if (RELU) {
        o.x = fmaxf(o.x, 0.f); o.y = fmaxf(o.y, 0.f);
        o.z = fmaxf(o.z, 0.f); o.w = fmaxf(o.w, 0.f);
    }
    dst[(long)w * DV + lane] = o;
}

extern "C" void kernel_launch(void* const* d_in, const int* in_sizes, int n_in,
                              void* d_out, int out_size) {
    const float* x  = (const float*)d_in[0];
    const void*  ei = d_in[1];
    const float* W1 = (const float*)d_in[2];
    const float* b1 = (const float*)d_in[3];
    const float* W2 = (const float*)d_in[4];
    const float* b2 = (const float*)d_in[5];
    float* out = (float*)d_out;

    const int N = in_sizes[0] / D;
    const int E = in_sizes[1] / 2;

    float*    t_ptr = nullptr;
    float*    h_ptr = nullptr;
    unsigned* w1p   = nullptr;
    unsigned* w2p   = nullptr;
    cudaGetSymbolAddress((void**)&t_ptr, g_t);
    cudaGetSymbolAddress((void**)&h_ptr, g_h);
    cudaGetSymbolAddress((void**)&w1p,   g_w1p);
    cudaGetSymbolAddress((void**)&w2p,   g_w2p);

    const int T = 256;
    const int eGrid    = (E + T - 1) / T;
    const int aggGrid  = (N * 32 + T - 1) / T;
    const int gemmGrid = (N + 63) / 64;

    // Agg/GEMM commute: Agg(x)@W = Agg(x@W); bias+ReLU fold into agg.
    // Launch 3 fuses GEMM-1 with the (independent) edge scatter.
    k_prep<<<eGrid, T>>>(ei, E, W1, W2);                                  // 1
    k_scan_dis<<<1, 1024>>>(N, E);                                        // 2
    k_gemm_scatter<<<gemmGrid + eGrid, T>>>(x, w1p, t_ptr, N,             // 3
                                            ei, E, gemmGrid);
    k_agg<true, false><<<aggGrid, T>>>((const float4*)t_ptr,              // 4
                                       (const float4*)b1, (float4*)h_ptr, N);
    k_gemm_tf32<<<gemmGrid, T>>>(h_ptr, w2p, t_ptr, N);                   // 5
    k_agg<false, true><<<aggGrid, T>>>((const float4*)t_ptr,              // 6
                                       (const float4*)b2, (float4*)out, N);
}

// round 11
// speedup vs baseline: 1.1992x; 1.0471x over previous
#include <cuda_runtime.h>
#include <cuda_fp16.h>
#include <stdint.h>

#define D 128
#define DV 32
#define MAXN 50048
#define MAXE 1600000

// Zero-initialized at module load. Invariant: g_deg and g_cnt are all-zero at
// entry to kernel_launch, and every call restores that before it returns
// (k_scan_dis zeroes deg; the final k_agg zeroes cnt).
__device__ int      g_deg[MAXN];
__device__ int      g_cnt[MAXN];
__device__ int2     g_adj[MAXE];        // dst-sorted: {src, bits(dis[src])}
__device__ int      g_start[MAXN + 1];  // CSR offsets by dst
__device__ float    g_dis[MAXN];
__device__ __half   g_th[MAXN * D];     // GEMM output (pre-aggregation), fp16
__device__ float    g_h[MAXN * D];      // hidden after layer 1 (fp32)
__device__ unsigned g_w1p[D * D];       // W1, tf32 bits, lane-major fragment pack
__device__ unsigned g_w2p[D * D];       // W2, tf32 bits, lane-major fragment pack

__device__ __forceinline__ unsigned f2tf32(float f) {
    unsigned u;
    asm("cvt.rna.tf32.f32 %0, %1;" : "=r"(u) : "f"(f));
    return u;
}

// Lane-major fragment pack:
//   word i = (((kk4*4 + wn)*4 + ks)*2 + jj)*128 + lane*4 + c
//   j = jj*4 + c; nt = j>>1; b = j&1; t = lane&3; g = lane>>2
//   k = kk4*32 + ks*8 + t + b*4;  n = wn*32 + nt*8 + g
__device__ __forceinline__ void pack_w(unsigned* dst, const float* __restrict__ W, int i) {
    int c    = i & 3;
    int lane = (i >> 2) & 31;
    int jj   = (i >> 7) & 1;
    int ks   = (i >> 8) & 3;
    int wn   = (i >> 10) & 3;
    int kk4  = i >> 12;
    int j  = jj * 4 + c;
    int nt = j >> 1;
    int b  = j & 1;
    int t  = lane & 3;
    int g  = lane >> 2;
    int k = kk4 * 32 + ks * 8 + t + b * 4;
    int n = wn * 32 + nt * 8 + g;
    dst[i] = f2tf32(W[k * D + n]);
}

// ---------------------------------------------------------------------------
// Per-block dtype detect: int64 little-endian values < 2^32 -> odd 32-bit
// words all zero over 128 samples.
// ---------------------------------------------------------------------------
__device__ __forceinline__ int detect_is64(const unsigned* p, int* s_flag) {
    if (threadIdx.x == 0) *s_flag = 0;
    __syncthreads();
    if (threadIdx.x < 64) {
        unsigned nz = p[2 * threadIdx.x + 1] | p[2 * threadIdx.x + 129];
        if (nz) atomicOr(s_flag, 1);
    }
    __syncthreads();
    return *s_flag ? 0 : 1;
}

// Parse edges (either dtype), count degrees; first 128 blocks pack W1/W2.
__global__ void k_prep(const void* p, int E,
                       const float* __restrict__ W1, const float* __restrict__ W2) {
    __shared__ int s_flag;
    int is64 = detect_is64((const unsigned*)p, &s_flag);
    int gt = blockIdx.x * blockDim.x + threadIdx.x;
    if (gt < D * D)          pack_w(g_w1p, W1, gt);
    else if (gt < 2 * D * D) pack_w(g_w2p, W2, gt - D * D);
    int e = gt;
    if (e >= E) return;
    int r, c;
    if (is64) {
        const long long* q = (const long long*)p;
        r = (int)q[e];
        c = (int)q[(long long)E + e];
    } else {
        const int* q = (const int*)p;
        r = q[e];
        c = q[E + e];
    }
    atomicAdd(&g_deg[r], 1);
    atomicAdd(&g_cnt[c], 1);
}

// Single block: exclusive scan g_cnt -> g_start, zero cursors,
// dis = rsqrt(deg+1) (self loop), re-zero g_deg (invariant restore).
__global__ void k_scan_dis(int N, int E) {
    __shared__ int sh[1024];
    const int tid = threadIdx.x;
    const int per = (N + 1023) >> 10;
    const int base = tid * per;
    int s = 0;
    for (int i = 0; i < per; i++) {
        int idx = base + i;
        if (idx < N) s += g_cnt[idx];
    }
    sh[tid] = s;
    __syncthreads();
    for (int off = 1; off < 1024; off <<= 1) {
        int t = (tid >= off) ? sh[tid - off] : 0;
        __syncthreads();
        sh[tid] += t;
        __syncthreads();
    }
    int run = sh[tid] - s;
    for (int i = 0; i < per; i++) {
        int idx = base + i;
        if (idx < N) {
            int c = g_cnt[idx];
            g_start[idx] = run;
            run += c;
            g_cnt[idx] = 0;
            g_dis[idx] = rsqrtf((float)(g_deg[idx] + 1));
            g_deg[idx] = 0;
        }
    }
    if (tid == 0) g_start[N] = E;
}

// ---------------------------------------------------------------------------
// FUSED: blocks [0, gemmBlocks) run GEMM-1 (tf32, x @ W1 -> g_th, fp16 out);
//        blocks [gemmBlocks, ...) scatter edges into the adjacency.
// GEMM: BM=64, BN=128, 8 warps (2m x 4n), warp tile 32x32; A staged As[64][36]
// (contiguous STS, conflict-free LDS fragments); W via 2x coalesced LDG.128
// per slab from the lane-major pack. Epilogue stores __half2.
// ---------------------------------------------------------------------------
__global__ void __launch_bounds__(256, 3)
k_gemm_scatter(const float* __restrict__ A, const unsigned* __restrict__ Wp,
               __half* __restrict__ C, int N,
               const void* p, int E, int gemmBlocks) {
    __shared__ unsigned As[64][36];

    if (blockIdx.x >= gemmBlocks) {
        // ---------------- scatter branch ----------------
        int is64 = detect_is64((const unsigned*)p, (int*)&As[0][0]);
        int e = (blockIdx.x - gemmBlocks) * blockDim.x + threadIdx.x;
        if (e >= E) return;
        int r, c;
        if (is64) {
            const long long* q = (const long long*)p;
            r = (int)q[e];
            c = (int)q[(long long)E + e];
        } else {
            const int* q = (const int*)p;
            r = q[e];
            c = q[E + e];
        }
        int pos = g_start[c] + atomicAdd(&g_cnt[c], 1);
        g_adj[pos] = make_int2(r, __float_as_int(g_dis[r]));
        return;
    }

    // ---------------- GEMM branch ----------------
    const int tid  = threadIdx.x;
    const int wid  = tid >> 5;
    const int lane = tid & 31;
    const int g    = lane >> 2;
    const int t    = lane & 3;
    const int wm   = wid >> 2;
    const int wn   = wid & 3;
    const int row0 = blockIdx.x * 64;

    float acc[2][4][4];
    #pragma unroll
    for (int mt = 0; mt < 2; mt++)
        #pragma unroll
        for (int nt = 0; nt < 4; nt++)
            #pragma unroll
            for (int c = 0; c < 4; c++) acc[mt][nt][c] = 0.f;

    for (int kk4 = 0; kk4 < 4; kk4++) {
        const int kk = kk4 * 32;
        #pragma unroll
        for (int it = 0; it < 2; it++) {
            int idx = tid + it * 256;
            int m  = idx >> 3;
            int k4 = idx & 7;
            float4 v = make_float4(0.f, 0.f, 0.f, 0.f);
            int gr = row0 + m;
            if (gr < N) v = *(const float4*)(A + (long)gr * D + kk + k4 * 4);
            As[m][k4 * 4 + 0] = f2tf32(v.x);
            As[m][k4 * 4 + 1] = f2tf32(v.y);
            As[m][k4 * 4 + 2] = f2tf32(v.z);
            As[m][k4 * 4 + 3] = f2tf32(v.w);
        }
        __syncthreads();

        const unsigned* wsl = Wp + ((kk4 * 4 + wn) * 4) * 256 + lane * 4;
        #pragma unroll
        for (int ks = 0; ks < 4; ks++) {
            uint4 u0 = __ldg((const uint4*)(wsl + ks * 256));
            uint4 u1 = __ldg((const uint4*)(wsl + ks * 256 + 128));
            unsigned bf[4][2] = {{u0.x, u0.y}, {u0.z, u0.w},
                                 {u1.x, u1.y}, {u1.z, u1.w}};
            #pragma unroll
            for (int mt = 0; mt < 2; mt++) {
                int mb = wm * 32 + mt * 16;
                unsigned a0 = As[mb + g    ][ks * 8 + t    ];
                unsigned a1 = As[mb + g + 8][ks * 8 + t    ];
                unsigned a2 = As[mb + g    ][ks * 8 + t + 4];
                unsigned a3 = As[mb + g + 8][ks * 8 + t + 4];
                #pragma unroll
                for (int nt = 0; nt < 4; nt++) {
                    asm volatile(
                        "mma.sync.aligned.m16n8k8.row.col.f32.tf32.tf32.f32 "
                        "{%0,%1,%2,%3}, {%4,%5,%6,%7}, {%8,%9}, {%0,%1,%2,%3};"
                        : "+f"(acc[mt][nt][0]), "+f"(acc[mt][nt][1]),
                          "+f"(acc[mt][nt][2]), "+f"(acc[mt][nt][3])
                        : "r"(a0), "r"(a1), "r"(a2), "r"(a3),
                          "r"(bf[nt][0]), "r"(bf[nt][1]));
                }
            }
        }
        __syncthreads();
    }

    #pragma unroll
    for (int mt = 0; mt < 2; mt++) {
        int r0 = row0 + wm * 32 + mt * 16 + g;
        int r1 = r0 + 8;
        #pragma unroll
        for (int nt = 0; nt < 4; nt++) {
            int n = wn * 32 + nt * 8 + 2 * t;
            if (r0 < N)
                *(__half2*)(C + (long)r0 * D + n) = __floats2half2_rn(acc[mt][nt][0], acc[mt][nt][1]);
            if (r1 < N)
                *(__half2*)(C + (long)r1 * D + n) = __floats2half2_rn(acc[mt][nt][2], acc[mt][nt][3]);
        }
    }
}

// Standalone GEMM (layer 2), identical math, fp16 output.
__global__ void __launch_bounds__(256, 3)
k_gemm_tf32(const float* __restrict__ A, const unsigned* __restrict__ Wp,
            __half* __restrict__ C, int N) {
    __shared__ unsigned As[64][36];

    const int tid  = threadIdx.x;
    const int wid  = tid >> 5;
    const int lane = tid & 31;
    const int g    = lane >> 2;
    const int t    = lane & 3;
    const int wm   = wid >> 2;
    const int wn   = wid & 3;
    const int row0 = blockIdx.x * 64;

    float acc[2][4][4];
    #pragma unroll
    for (int mt = 0; mt < 2; mt++)
        #pragma unroll
        for (int nt = 0; nt < 4; nt++)
            #pragma unroll
            for (int c = 0; c < 4; c++) acc[mt][nt][c] = 0.f;

    for (int kk4 = 0; kk4 < 4; kk4++) {
        const int kk = kk4 * 32;
        #pragma unroll
        for (int it = 0; it < 2; it++) {
            int idx = tid + it * 256;
            int m  = idx >> 3;
            int k4 = idx & 7;
            float4 v = make_float4(0.f, 0.f, 0.f, 0.f);
            int gr = row0 + m;
            if (gr < N) v = *(const float4*)(A + (long)gr * D + kk + k4 * 4);
            As[m][k4 * 4 + 0] = f2tf32(v.x);
            As[m][k4 * 4 + 1] = f2tf32(v.y);
            As[m][k4 * 4 + 2] = f2tf32(v.z);
            As[m][k4 * 4 + 3] = f2tf32(v.w);
        }
        __syncthreads();

        const unsigned* wsl = Wp + ((kk4 * 4 + wn) * 4) * 256 + lane * 4;
        #pragma unroll
        for (int ks = 0; ks < 4; ks++) {
            uint4 u0 = __ldg((const uint4*)(wsl + ks * 256));
            uint4 u1 = __ldg((const uint4*)(wsl + ks * 256 + 128));
            unsigned bf[4][2] = {{u0.x, u0.y}, {u0.z, u0.w},
                                 {u1.x, u1.y}, {u1.z, u1.w}};
            #pragma unroll
            for (int mt = 0; mt < 2; mt++) {
                int mb = wm * 32 + mt * 16;
                unsigned a0 = As[mb + g    ][ks * 8 + t    ];
                unsigned a1 = As[mb + g + 8][ks * 8 + t    ];
                unsigned a2 = As[mb + g    ][ks * 8 + t + 4];
                unsigned a3 = As[mb + g + 8][ks * 8 + t + 4];
                #pragma unroll
                for (int nt = 0; nt < 4; nt++) {
                    asm volatile(
                        "mma.sync.aligned.m16n8k8.row.col.f32.tf32.tf32.f32 "
                        "{%0,%1,%2,%3}, {%4,%5,%6,%7}, {%8,%9}, {%0,%1,%2,%3};"
                        : "+f"(acc[mt][nt][0]), "+f"(acc[mt][nt][1]),
                          "+f"(acc[mt][nt][2]), "+f"(acc[mt][nt][3])
                        : "r"(a0), "r"(a1), "r"(a2), "r"(a3),
                          "r"(bf[nt][0]), "r"(bf[nt][1]));
                }
            }
        }
        __syncthreads();
    }

    #pragma unroll
    for (int mt = 0; mt < 2; mt++) {
        int r0 = row0 + wm * 32 + mt * 16 + g;
        int r1 = r0 + 8;
        #pragma unroll
        for (int nt = 0; nt < 4; nt++) {
            int n = wn * 32 + nt * 8 + 2 * t;
            if (r0 < N)
                *(__half2*)(C + (long)r0 * D + n) = __floats2half2_rn(acc[mt][nt][0], acc[mt][nt][1]);
            if (r1 < N)
                *(__half2*)(C + (long)r1 * D + n) = __floats2half2_rn(acc[mt][nt][2], acc[mt][nt][3]);
        }
    }
}

// ---------------------------------------------------------------------------
// Aggregation (+ bias, optional ReLU): one warp per dst node, fp16 gather
// (256B/row -> 2 L1 wavefronts/edge instead of 4), fp32 accumulation,
// low-reg 2-accumulator structure, adjacency read as int4 (2 edges/load).
// out = dis[n]*(sum_e dis[src]*t[src]) + dis[n]^2 * t[n] + bias
// ---------------------------------------------------------------------------
template <bool RELU, bool CLEAN>
__global__ void __launch_bounds__(256)
k_agg(const uint2* __restrict__ src, const float4* __restrict__ bias4,
      float4* __restrict__ dst, int N) {
    if (CLEAN) {
        int idx = blockIdx.x * blockDim.x + threadIdx.x;
        if (idx < MAXN) g_cnt[idx] = 0;   // restore invariant
    }
    int w = (blockIdx.x * blockDim.x + threadIdx.x) >> 5;
    if (w >= N) return;
    const int lane = threadIdx.x & 31;
    int i = g_start[w];
    const int end = g_start[w + 1];

    float4 a0 = make_float4(0.f, 0.f, 0.f, 0.f);
    float4 a1 = make_float4(0.f, 0.f, 0.f, 0.f);

    // Peel to even index so int4 adjacency loads are 16B-aligned.
    if ((i & 1) && i < end) {
        int2 e = __ldg(&g_adj[i]);
        uint2 p = __ldg(&src[(long)e.x * 32 + lane]);
        float ww = __int_as_float(e.y);
        float2 fa = __half22float2(*(__half2*)&p.x);
        float2 fb = __half22float2(*(__half2*)&p.y);
        a0.x += ww * fa.x; a0.y += ww * fa.y; a0.z += ww * fb.x; a0.w += ww * fb.y;
        i++;
    }
    for (; i + 4 <= end; i += 4) {
        int4 eA = __ldg((const int4*)&g_adj[i]);       // edges i, i+1
        int4 eB = __ldg((const int4*)&g_adj[i + 2]);   // edges i+2, i+3
        uint2 p0 = __ldg(&src[(long)eA.x * 32 + lane]);
        uint2 p1 = __ldg(&src[(long)eA.z * 32 + lane]);
        uint2 p2 = __ldg(&src[(long)eB.x * 32 + lane]);
        uint2 p3 = __ldg(&src[(long)eB.z * 32 + lane]);
        float w0 = __int_as_float(eA.y);
        float w1 = __int_as_float(eA.w);
        float w2 = __int_as_float(eB.y);
        float w3 = __int_as_float(eB.w);
        float2 f;
        f = __half22float2(*(__half2*)&p0.x); a0.x += w0 * f.x; a0.y += w0 * f.y;
        f = __half22float2(*(__half2*)&p0.y); a0.z += w0 * f.x; a0.w += w0 * f.y;
        f = __half22float2(*(__half2*)&p1.x); a1.x += w1 * f.x; a1.y += w1 * f.y;
        f = __half22float2(*(__half2*)&p1.y); a1.z += w1 * f.x; a1.w += w1 * f.y;
        f = __half22float2(*(__half2*)&p2.x); a0.x += w2 * f.x; a0.y += w2 * f.y;
        f = __half22float2(*(__half2*)&p2.y); a0.z += w2 * f.x; a0.w += w2 * f.y;
        f = __half22float2(*(__half2*)&p3.x); a1.x += w3 * f.x; a1.y += w3 * f.y;
        f = __half22float2(*(__half2*)&p3.y); a1.z += w3 * f.x; a1.w += w3 * f.y;
    }
    for (; i < end; i++) {
        int2 e = __ldg(&g_adj[i]);
        uint2 p = __ldg(&src[(long)e.x * 32 + lane]);
        float ww = __int_as_float(e.y);
        float2 fa = __half22float2(*(__half2*)&p.x);
        float2 fb = __half22float2(*(__half2*)&p.y);
        a0.x += ww * fa.x; a0.y += ww * fa.y; a0.z += ww * fb.x; a0.w += ww * fb.y;
    }

    float di = g_dis[w];
    float sw = di * di;
    uint2 ps = __ldg(&src[(long)w * 32 + lane]);
    float2 s0 = __half22float2(*(__half2*)&ps.x);
    float2 s1 = __half22float2(*(__half2*)&ps.y);
    float4 bv = __ldg(&bias4[lane]);
    float4 o;
    o.x = di * (a0.x + a1.x) + sw * s0.x + bv.x;
    o.y = di * (a0.y + a1.y) + sw * s0.y + bv.y;
    o.z = di * (a0.z + a1.z) + sw * s1.x + bv.z;
    o.w = di * (a0.w + a1.w) + sw * s1.y + bv.w;
    if (RELU) {
        o.x = fmaxf(o.x, 0.f); o.y = fmaxf(o.y, 0.f);
        o.z = fmaxf(o.z, 0.f); o.w = fmaxf(o.w, 0.f);
    }
    dst[(long)w * DV + lane] = o;
}

extern "C" void kernel_launch(void* const* d_in, const int* in_sizes, int n_in,
                              void* d_out, int out_size) {
    const float* x  = (const float*)d_in[0];
    const void*  ei = d_in[1];
    const float* W1 = (const float*)d_in[2];
    const float* b1 = (const float*)d_in[3];
    const float* W2 = (const float*)d_in[4];
    const float* b2 = (const float*)d_in[5];
    float* out = (float*)d_out;

    const int N = in_sizes[0] / D;
    const int E = in_sizes[1] / 2;

    __half*   th_ptr = nullptr;
    float*    h_ptr  = nullptr;
    unsigned* w1p    = nullptr;
    unsigned* w2p    = nullptr;
    cudaGetSymbolAddress((void**)&th_ptr, g_th);
    cudaGetSymbolAddress((void**)&h_ptr,  g_h);
    cudaGetSymbolAddress((void**)&w1p,    g_w1p);
    cudaGetSymbolAddress((void**)&w2p,    g_w2p);

    const int T = 256;
    const int eGrid    = (E + T - 1) / T;
    const int aggGrid  = (N * 32 + T - 1) / T;
    const int gemmGrid = (N + 63) / 64;

    // Agg/GEMM commute: Agg(x)@W = Agg(x@W); bias+ReLU fold into agg.
    // GEMMs emit fp16 (halves agg gather wavefronts); agg accumulates fp32.
    k_prep<<<eGrid, T>>>(ei, E, W1, W2);                                  // 1
    k_scan_dis<<<1, 1024>>>(N, E);                                        // 2
    k_gemm_scatter<<<gemmGrid + eGrid, T>>>(x, w1p, th_ptr, N,            // 3
                                            ei, E, gemmGrid);
    k_agg<true, false><<<aggGrid, T>>>((const uint2*)th_ptr,              // 4
                                       (const float4*)b1, (float4*)h_ptr, N);
    k_gemm_tf32<<<gemmGrid, T>>>(h_ptr, w2p, th_ptr, N);                  // 5
    k_agg<false, true><<<aggGrid, T>>>((const uint2*)th_ptr,              // 6
                                       (const float4*)b2, (float4*)out, N);
}

// round 12
// speedup vs baseline: 1.2709x; 1.0598x over previous
#include <cuda_runtime.h>
#include <cuda_fp16.h>
#include <stdint.h>

#define D 128
#define DV 32
#define MAXN 50048
#define MAXE 1600000

// Zero-initialized at module load. Invariant: g_deg and g_cnt are all-zero at
// entry to kernel_launch, and every call restores that before it returns
// (k_scan_dis zeroes deg; the final k_agg zeroes cnt).
__device__ int      g_deg[MAXN];
__device__ int      g_cnt[MAXN];
__device__ int2     g_adj[MAXE];        // dst-sorted: {src, bits(dis[src])}
__device__ int      g_start[MAXN + 1];  // CSR offsets by dst
__device__ float    g_dis[MAXN];
__device__ __half   g_th[MAXN * D];     // GEMM output (pre-aggregation), fp16
__device__ float    g_h[MAXN * D];      // hidden after layer 1 (fp32)
__device__ unsigned g_w1p[D * D];       // W1, tf32 bits, lane-major fragment pack
__device__ unsigned g_w2p[D * D];       // W2, tf32 bits, lane-major fragment pack

__device__ __forceinline__ unsigned f2tf32(float f) {
    unsigned u;
    asm("cvt.rna.tf32.f32 %0, %1;" : "=r"(u) : "f"(f));
    return u;
}

// Lane-major fragment pack:
//   word i = (((kk4*4 + wn)*4 + ks)*2 + jj)*128 + lane*4 + c
//   j = jj*4 + c; nt = j>>1; b = j&1; t = lane&3; g = lane>>2
//   k = kk4*32 + ks*8 + t + b*4;  n = wn*32 + nt*8 + g
__device__ __forceinline__ void pack_w(unsigned* dst, const float* __restrict__ W, int i) {
    int c    = i & 3;
    int lane = (i >> 2) & 31;
    int jj   = (i >> 7) & 1;
    int ks   = (i >> 8) & 3;
    int wn   = (i >> 10) & 3;
    int kk4  = i >> 12;
    int j  = jj * 4 + c;
    int nt = j >> 1;
    int b  = j & 1;
    int t  = lane & 3;
    int g  = lane >> 2;
    int k = kk4 * 32 + ks * 8 + t + b * 4;
    int n = wn * 32 + nt * 8 + g;
    dst[i] = f2tf32(W[k * D + n]);
}

// ---------------------------------------------------------------------------
// Per-block dtype detect: int64 little-endian values < 2^32 -> odd 32-bit
// words all zero over 128 samples.
// ---------------------------------------------------------------------------
__device__ __forceinline__ int detect_is64(const unsigned* p, int* s_flag) {
    if (threadIdx.x == 0) *s_flag = 0;
    __syncthreads();
    if (threadIdx.x < 64) {
        unsigned nz = p[2 * threadIdx.x + 1] | p[2 * threadIdx.x + 129];
        if (nz) atomicOr(s_flag, 1);
    }
    __syncthreads();
    return *s_flag ? 0 : 1;
}

// Parse edges (either dtype), count degrees.
__global__ void k_prep(const void* p, int E) {
    __shared__ int s_flag;
    int is64 = detect_is64((const unsigned*)p, &s_flag);
    int e = blockIdx.x * blockDim.x + threadIdx.x;
    if (e >= E) return;
    int r, c;
    if (is64) {
        const long long* q = (const long long*)p;
        r = (int)q[e];
        c = (int)q[(long long)E + e];
    } else {
        const int* q = (const int*)p;
        r = q[e];
        c = q[E + e];
    }
    atomicAdd(&g_deg[r], 1);
    atomicAdd(&g_cnt[c], 1);
}

// ---------------------------------------------------------------------------
// Block 0 (1024 thr): exclusive scan g_cnt -> g_start (shfl warp-scan,
// 2 barriers), zero cursors, dis = rsqrt(deg+1), re-zero deg. Batched
// independent loads so L2 latency pipelines.
// Blocks 1..32: pack W1/W2 into lane-major tf32 fragment layout (the scan
// block leaves the rest of the chip idle; the pack rides along free).
// ---------------------------------------------------------------------------
__global__ void k_scan_dis(int N, int E,
                           const float* __restrict__ W1, const float* __restrict__ W2) {
    if (blockIdx.x > 0) {
        int i = (blockIdx.x - 1) * 1024 + threadIdx.x;   // 0 .. 32767
        if (i < D * D) pack_w(g_w1p, W1, i);
        else           pack_w(g_w2p, W2, i - D * D);
        return;
    }

    __shared__ int warpBase[32];
    const int tid  = threadIdx.x;
    const int lane = tid & 31;
    const int wid  = tid >> 5;
    const int per  = (N + 1023) >> 10;
    const int base = tid * per;

    // Phase A: per-thread sum with 4-wide independent loads.
    int s = 0;
    {
        int i = 0;
        for (; i + 4 <= per; i += 4) {
            int i0 = base + i;
            int c0 = (i0     < N) ? g_cnt[i0]     : 0;
            int c1 = (i0 + 1 < N) ? g_cnt[i0 + 1] : 0;
            int c2 = (i0 + 2 < N) ? g_cnt[i0 + 2] : 0;
            int c3 = (i0 + 3 < N) ? g_cnt[i0 + 3] : 0;
            s += (c0 + c1) + (c2 + c3);
        }
        for (; i < per; i++) {
            int i0 = base + i;
            if (i0 < N) s += g_cnt[i0];
        }
    }

    // Warp-inclusive scan of thread sums.
    int incl = s;
    #pragma unroll
    for (int off = 1; off < 32; off <<= 1) {
        int v = __shfl_up_sync(0xffffffffu, incl, off);
        if (lane >= off) incl += v;
    }
    if (lane == 31) warpBase[wid] = incl;   // warp totals
    __syncthreads();
    if (wid == 0) {
        int wv = warpBase[lane];
        int wi = wv;
        #pragma unroll
        for (int off = 1; off < 32; off <<= 1) {
            int v = __shfl_up_sync(0xffffffffu, wi, off);
            if (lane >= off) wi += v;
        }
        warpBase[lane] = wi - wv;           // exclusive warp base
    }
    __syncthreads();
    int run = warpBase[wid] + (incl - s);   // thread's exclusive global prefix

    // Phase B: emit offsets, zero cursors, compute dis, restore deg=0.
    {
        int i = 0;
        for (; i + 4 <= per; i += 4) {
            int i0 = base + i;
            int c0 = (i0     < N) ? g_cnt[i0]     : 0;
            int c1 = (i0 + 1 < N) ? g_cnt[i0 + 1] : 0;
            int c2 = (i0 + 2 < N) ? g_cnt[i0 + 2] : 0;
            int c3 = (i0 + 3 < N) ? g_cnt[i0 + 3] : 0;
            int d0 = (i0     < N) ? g_deg[i0]     : 0;
            int d1 = (i0 + 1 < N) ? g_deg[i0 + 1] : 0;
            int d2 = (i0 + 2 < N) ? g_deg[i0 + 2] : 0;
            int d3 = (i0 + 3 < N) ? g_deg[i0 + 3] : 0;
            if (i0 < N) {
                g_start[i0] = run;  g_cnt[i0] = 0;  g_deg[i0] = 0;
                g_dis[i0] = rsqrtf((float)(d0 + 1));
            }
            if (i0 + 1 < N) {
                g_start[i0 + 1] = run + c0;  g_cnt[i0 + 1] = 0;  g_deg[i0 + 1] = 0;
                g_dis[i0 + 1] = rsqrtf((float)(d1 + 1));
            }
            if (i0 + 2 < N) {
                g_start[i0 + 2] = run + c0 + c1;  g_cnt[i0 + 2] = 0;  g_deg[i0 + 2] = 0;
                g_dis[i0 + 2] = rsqrtf((float)(d2 + 1));
            }
            if (i0 + 3 < N) {
                g_start[i0 + 3] = run + c0 + c1 + c2;  g_cnt[i0 + 3] = 0;  g_deg[i0 + 3] = 0;
                g_dis[i0 + 3] = rsqrtf((float)(d3 + 1));
            }
            run += (c0 + c1) + (c2 + c3);
        }
        for (; i < per; i++) {
            int i0 = base + i;
            if (i0 < N) {
                int c = g_cnt[i0];
                g_start[i0] = run;  run += c;
                g_cnt[i0] = 0;
                g_dis[i0] = rsqrtf((float)(g_deg[i0] + 1));
                g_deg[i0] = 0;
            }
        }
    }
    if (tid == 0) g_start[N] = E;
}

// ---------------------------------------------------------------------------
// FUSED: blocks [0, gemmBlocks) run GEMM-1 (tf32, x @ W1 -> g_th, fp16 out);
//        blocks [gemmBlocks, ...) scatter edges into the adjacency.
// ---------------------------------------------------------------------------
__global__ void __launch_bounds__(256, 3)
k_gemm_scatter(const float* __restrict__ A, const unsigned* __restrict__ Wp,
               __half* __restrict__ C, int N,
               const void* p, int E, int gemmBlocks) {
    __shared__ unsigned As[64][36];

    if (blockIdx.x >= gemmBlocks) {
        // ---------------- scatter branch ----------------
        int is64 = detect_is64((const unsigned*)p, (int*)&As[0][0]);
        int e = (blockIdx.x - gemmBlocks) * blockDim.x + threadIdx.x;
        if (e >= E) return;
        int r, c;
        if (is64) {
            const long long* q = (const long long*)p;
            r = (int)q[e];
            c = (int)q[(long long)E + e];
        } else {
            const int* q = (const int*)p;
            r = q[e];
            c = q[E + e];
        }
        int pos = g_start[c] + atomicAdd(&g_cnt[c], 1);
        g_adj[pos] = make_int2(r, __float_as_int(g_dis[r]));
        return;
    }

    // ---------------- GEMM branch ----------------
    const int tid  = threadIdx.x;
    const int wid  = tid >> 5;
    const int lane = tid & 31;
    const int g    = lane >> 2;
    const int t    = lane & 3;
    const int wm   = wid >> 2;
    const int wn   = wid & 3;
    const int row0 = blockIdx.x * 64;

    float acc[2][4][4];
    #pragma unroll
    for (int mt = 0; mt < 2; mt++)
        #pragma unroll
        for (int nt = 0; nt < 4; nt++)
            #pragma unroll
            for (int c = 0; c < 4; c++) acc[mt][nt][c] = 0.f;

    for (int kk4 = 0; kk4 < 4; kk4++) {
        const int kk = kk4 * 32;
        #pragma unroll
        for (int it = 0; it < 2; it++) {
            int idx = tid + it * 256;
            int m  = idx >> 3;
            int k4 = idx & 7;
            float4 v = make_float4(0.f, 0.f, 0.f, 0.f);
            int gr = row0 + m;
            if (gr < N) v = *(const float4*)(A + (long)gr * D + kk + k4 * 4);
            As[m][k4 * 4 + 0] = f2tf32(v.x);
            As[m][k4 * 4 + 1] = f2tf32(v.y);
            As[m][k4 * 4 + 2] = f2tf32(v.z);
            As[m][k4 * 4 + 3] = f2tf32(v.w);
        }
        __syncthreads();

        const unsigned* wsl = Wp + ((kk4 * 4 + wn) * 4) * 256 + lane * 4;
        #pragma unroll
        for (int ks = 0; ks < 4; ks++) {
            uint4 u0 = __ldg((const uint4*)(wsl + ks * 256));
            uint4 u1 = __ldg((const uint4*)(wsl + ks * 256 + 128));
            unsigned bf[4][2] = {{u0.x, u0.y}, {u0.z, u0.w},
                                 {u1.x, u1.y}, {u1.z, u1.w}};
            #pragma unroll
            for (int mt = 0; mt < 2; mt++) {
                int mb = wm * 32 + mt * 16;
                unsigned a0 = As[mb + g    ][ks * 8 + t    ];
                unsigned a1 = As[mb + g + 8][ks * 8 + t    ];
                unsigned a2 = As[mb + g    ][ks * 8 + t + 4];
                unsigned a3 = As[mb + g + 8][ks * 8 + t + 4];
                #pragma unroll
                for (int nt = 0; nt < 4; nt++) {
                    asm volatile(
                        "mma.sync.aligned.m16n8k8.row.col.f32.tf32.tf32.f32 "
                        "{%0,%1,%2,%3}, {%4,%5,%6,%7}, {%8,%9}, {%0,%1,%2,%3};"
                        : "+f"(acc[mt][nt][0]), "+f"(acc[mt][nt][1]),
                          "+f"(acc[mt][nt][2]), "+f"(acc[mt][nt][3])
                        : "r"(a0), "r"(a1), "r"(a2), "r"(a3),
                          "r"(bf[nt][0]), "r"(bf[nt][1]));
                }
            }
        }
        __syncthreads();
    }

    #pragma unroll
    for (int mt = 0; mt < 2; mt++) {
        int r0 = row0 + wm * 32 + mt * 16 + g;
        int r1 = r0 + 8;
        #pragma unroll
        for (int nt = 0; nt < 4; nt++) {
            int n = wn * 32 + nt * 8 + 2 * t;
            if (r0 < N)
                *(__half2*)(C + (long)r0 * D + n) = __floats2half2_rn(acc[mt][nt][0], acc[mt][nt][1]);
            if (r1 < N)
                *(__half2*)(C + (long)r1 * D + n) = __floats2half2_rn(acc[mt][nt][2], acc[mt][nt][3]);
        }
    }
}

// Standalone GEMM (layer 2), identical math, fp16 output.
__global__ void __launch_bounds__(256, 3)
k_gemm_tf32(const float* __restrict__ A, const unsigned* __restrict__ Wp,
            __half* __restrict__ C, int N) {
    __shared__ unsigned As[64][36];

    const int tid  = threadIdx.x;
    const int wid  = tid >> 5;
    const int lane = tid & 31;
    const int g    = lane >> 2;
    const int t    = lane & 3;
    const int wm   = wid >> 2;
    const int wn   = wid & 3;
    const int row0 = blockIdx.x * 64;

    float acc[2][4][4];
    #pragma unroll
    for (int mt = 0; mt < 2; mt++)
        #pragma unroll
        for (int nt = 0; nt < 4; nt++)
            #pragma unroll
            for (int c = 0; c < 4; c++) acc[mt][nt][c] = 0.f;

    for (int kk4 = 0; kk4 < 4; kk4++) {
        const int kk = kk4 * 32;
        #pragma unroll
        for (int it = 0; it < 2; it++) {
            int idx = tid + it * 256;
            int m  = idx >> 3;
            int k4 = idx & 7;
            float4 v = make_float4(0.f, 0.f, 0.f, 0.f);
            int gr = row0 + m;
            if (gr < N) v = *(const float4*)(A + (long)gr * D + kk + k4 * 4);
            As[m][k4 * 4 + 0] = f2tf32(v.x);
            As[m][k4 * 4 + 1] = f2tf32(v.y);
            As[m][k4 * 4 + 2] = f2tf32(v.z);
            As[m][k4 * 4 + 3] = f2tf32(v.w);
        }
        __syncthreads();

        const unsigned* wsl = Wp + ((kk4 * 4 + wn) * 4) * 256 + lane * 4;
        #pragma unroll
        for (int ks = 0; ks < 4; ks++) {
            uint4 u0 = __ldg((const uint4*)(wsl + ks * 256));
            uint4 u1 = __ldg((const uint4*)(wsl + ks * 256 + 128));
            unsigned bf[4][2] = {{u0.x, u0.y}, {u0.z, u0.w},
                                 {u1.x, u1.y}, {u1.z, u1.w}};
            #pragma unroll
            for (int mt = 0; mt < 2; mt++) {
                int mb = wm * 32 + mt * 16;
                unsigned a0 = As[mb + g    ][ks * 8 + t    ];
                unsigned a1 = As[mb + g + 8][ks * 8 + t    ];
                unsigned a2 = As[mb + g    ][ks * 8 + t + 4];
                unsigned a3 = As[mb + g + 8][ks * 8 + t + 4];
                #pragma unroll
                for (int nt = 0; nt < 4; nt++) {
                    asm volatile(
                        "mma.sync.aligned.m16n8k8.row.col.f32.tf32.tf32.f32 "
                        "{%0,%1,%2,%3}, {%4,%5,%6,%7}, {%8,%9}, {%0,%1,%2,%3};"
                        : "+f"(acc[mt][nt][0]), "+f"(acc[mt][nt][1]),
                          "+f"(acc[mt][nt][2]), "+f"(acc[mt][nt][3])
                        : "r"(a0), "r"(a1), "r"(a2), "r"(a3),
                          "r"(bf[nt][0]), "r"(bf[nt][1]));
                }
            }
        }
        __syncthreads();
    }

    #pragma unroll
    for (int mt = 0; mt < 2; mt++) {
        int r0 = row0 + wm * 32 + mt * 16 + g;
        int r1 = r0 + 8;
        #pragma unroll
        for (int nt = 0; nt < 4; nt++) {
            int n = wn * 32 + nt * 8 + 2 * t;
            if (r0 < N)
                *(__half2*)(C + (long)r0 * D + n) = __floats2half2_rn(acc[mt][nt][0], acc[mt][nt][1]);
            if (r1 < N)
                *(__half2*)(C + (long)r1 * D + n) = __floats2half2_rn(acc[mt][nt][2], acc[mt][nt][3]);
        }
    }
}

// ---------------------------------------------------------------------------
// Aggregation (+ bias, optional ReLU): one warp per dst node, fp16 gather,
// fp32 accumulation, int4 adjacency loads (2 edges/load).
// out = dis[n]*(sum_e dis[src]*t[src]) + dis[n]^2 * t[n] + bias
// ---------------------------------------------------------------------------
template <bool RELU, bool CLEAN>
__global__ void __launch_bounds__(256)
k_agg(const uint2* __restrict__ src, const float4* __restrict__ bias4,
      float4* __restrict__ dst, int N) {
    if (CLEAN) {
        int idx = blockIdx.x * blockDim.x + threadIdx.x;
        if (idx < MAXN) g_cnt[idx] = 0;   // restore invariant
    }
    int w = (blockIdx.x * blockDim.x + threadIdx.x) >> 5;
    if (w >= N) return;
    const int lane = threadIdx.x & 31;
    int i = g_start[w];
    const int end = g_start[w + 1];

    float4 a0 = make_float4(0.f, 0.f, 0.f, 0.f);
    float4 a1 = make_float4(0.f, 0.f, 0.f, 0.f);

    if ((i & 1) && i < end) {
        int2 e = __ldg(&g_adj[i]);
        uint2 p = __ldg(&src[(long)e.x * 32 + lane]);
        float ww = __int_as_float(e.y);
        float2 fa = __half22float2(*(__half2*)&p.x);
        float2 fb = __half22float2(*(__half2*)&p.y);
        a0.x += ww * fa.x; a0.y += ww * fa.y; a0.z += ww * fb.x; a0.w += ww * fb.y;
        i++;
    }
    for (; i + 4 <= end; i += 4) {
        int4 eA = __ldg((const int4*)&g_adj[i]);
        int4 eB = __ldg((const int4*)&g_adj[i + 2]);
        uint2 p0 = __ldg(&src[(long)eA.x * 32 + lane]);
        uint2 p1 = __ldg(&src[(long)eA.z * 32 + lane]);
        uint2 p2 = __ldg(&src[(long)eB.x * 32 + lane]);
        uint2 p3 = __ldg(&src[(long)eB.z * 32 + lane]);
        float w0 = __int_as_float(eA.y);
        float w1 = __int_as_float(eA.w);
        float w2 = __int_as_float(eB.y);
        float w3 = __int_as_float(eB.w);
        float2 f;
        f = __half22float2(*(__half2*)&p0.x); a0.x += w0 * f.x; a0.y += w0 * f.y;
        f = __half22float2(*(__half2*)&p0.y); a0.z += w0 * f.x; a0.w += w0 * f.y;
        f = __half22float2(*(__half2*)&p1.x); a1.x += w1 * f.x; a1.y += w1 * f.y;
        f = __half22float2(*(__half2*)&p1.y); a1.z += w1 * f.x; a1.w += w1 * f.y;
        f = __half22float2(*(__half2*)&p2.x); a0.x += w2 * f.x; a0.y += w2 * f.y;
        f = __half22float2(*(__half2*)&p2.y); a0.z += w2 * f.x; a0.w += w2 * f.y;
        f = __half22float2(*(__half2*)&p3.x); a1.x += w3 * f.x; a1.y += w3 * f.y;
        f = __half22float2(*(__half2*)&p3.y); a1.z += w3 * f.x; a1.w += w3 * f.y;
    }
    for (; i < end; i++) {
        int2 e = __ldg(&g_adj[i]);
        uint2 p = __ldg(&src[(long)e.x * 32 + lane]);
        float ww = __int_as_float(e.y);
        float2 fa = __half22float2(*(__half2*)&p.x);
        float2 fb = __half22float2(*(__half2*)&p.y);
        a0.x += ww * fa.x; a0.y += ww * fa.y; a0.z += ww * fb.x; a0.w += ww * fb.y;
    }

    float di = g_dis[w];
    float sw = di * di;
    uint2 ps = __ldg(&src[(long)w * 32 + lane]);
    float2 s0 = __half22float2(*(__half2*)&ps.x);
    float2 s1 = __half22float2(*(__half2*)&ps.y);
    float4 bv = __ldg(&bias4[lane]);
    float4 o;
    o.x = di * (a0.x + a1.x) + sw * s0.x + bv.x;
    o.y = di * (a0.y + a1.y) + sw * s0.y + bv.y;
    o.z = di * (a0.z + a1.z) + sw * s1.x + bv.z;
    o.w = di * (a0.w + a1.w) + sw * s1.y + bv.w;
    if (RELU) {
        o.x = fmaxf(o.x, 0.f); o.y = fmaxf(o.y, 0.f);
        o.z = fmaxf(o.z, 0.f); o.w = fmaxf(o.w, 0.f);
    }
    dst[(long)w * DV + lane] = o;
}

extern "C" void kernel_launch(void* const* d_in, const int* in_sizes, int n_in,
                              void* d_out, int out_size) {
    const float* x  = (const float*)d_in[0];
    const void*  ei = d_in[1];
    const float* W1 = (const float*)d_in[2];
    const float* b1 = (const float*)d_in[3];
    const float* W2 = (const float*)d_in[4];
    const float* b2 = (const float*)d_in[5];
    float* out = (float*)d_out;

    const int N = in_sizes[0] / D;
    const int E = in_sizes[1] / 2;

    __half*   th_ptr = nullptr;
    float*    h_ptr  = nullptr;
    unsigned* w1p    = nullptr;
    unsigned* w2p    = nullptr;
    cudaGetSymbolAddress((void**)&th_ptr, g_th);
    cudaGetSymbolAddress((void**)&h_ptr,  g_h);
    cudaGetSymbolAddress((void**)&w1p,    g_w1p);
    cudaGetSymbolAddress((void**)&w2p,    g_w2p);

    const int T = 256;
    const int eGrid    = (E + T - 1) / T;
    const int aggGrid  = (N * 32 + T - 1) / T;
    const int gemmGrid = (N + 63) / 64;

    // Agg/GEMM commute: Agg(x)@W = Agg(x@W); bias+ReLU fold into agg.
    // Scan launch carries the W-pack as free extra blocks.
    k_prep<<<eGrid, T>>>(ei, E);                                          // 1
    k_scan_dis<<<33, 1024>>>(N, E, W1, W2);                               // 2
    k_gemm_scatter<<<gemmGrid + eGrid, T>>>(x, w1p, th_ptr, N,            // 3
                                            ei, E, gemmGrid);
    k_agg<true, false><<<aggGrid, T>>>((const uint2*)th_ptr,              // 4
                                       (const float4*)b1, (float4*)h_ptr, N);
    k_gemm_tf32<<<gemmGrid, T>>>(h_ptr, w2p, th_ptr, N);                  // 5
    k_agg<false, true><<<aggGrid, T>>>((const uint2*)th_ptr,              // 6
                                       (const float4*)b2, (float4*)out, N);
}

// round 13
// speedup vs baseline: 1.2998x; 1.0227x over previous
#include <cuda_runtime.h>
#include <cuda_fp16.h>
#include <stdint.h>

#define D 128
#define DV 32
#define MAXN 50048
#define MAXE 1600000

// Zero-initialized at module load. Invariant: g_deg and g_cnt are all-zero at
// entry to kernel_launch, and every call restores that before it returns
// (k_scan_dis zeroes deg; the final k_agg zeroes cnt).
__device__ int      g_deg[MAXN];
__device__ int      g_cnt[MAXN];
__device__ int      g_adjs[MAXE];       // dst-sorted src ids (weights folded into t')
__device__ int      g_start[MAXN + 1];  // CSR offsets by dst
__device__ float    g_dis[MAXN];
__device__ __half   g_th[MAXN * D];     // dis[row] * (A@W) output, fp16
__device__ float    g_h[MAXN * D];      // hidden after layer 1 (fp32)
__device__ unsigned g_w1p[D * D];       // W1, tf32 bits, lane-major fragment pack
__device__ unsigned g_w2p[D * D];       // W2, tf32 bits, lane-major fragment pack

__device__ __forceinline__ unsigned f2tf32(float f) {
    unsigned u;
    asm("cvt.rna.tf32.f32 %0, %1;" : "=r"(u) : "f"(f));
    return u;
}

// Lane-major fragment pack:
//   word i = (((kk4*4 + wn)*4 + ks)*2 + jj)*128 + lane*4 + c
//   j = jj*4 + c; nt = j>>1; b = j&1; t = lane&3; g = lane>>2
//   k = kk4*32 + ks*8 + t + b*4;  n = wn*32 + nt*8 + g
__device__ __forceinline__ void pack_w(unsigned* dst, const float* __restrict__ W, int i) {
    int c    = i & 3;
    int lane = (i >> 2) & 31;
    int jj   = (i >> 7) & 1;
    int ks   = (i >> 8) & 3;
    int wn   = (i >> 10) & 3;
    int kk4  = i >> 12;
    int j  = jj * 4 + c;
    int nt = j >> 1;
    int b  = j & 1;
    int t  = lane & 3;
    int g  = lane >> 2;
    int k = kk4 * 32 + ks * 8 + t + b * 4;
    int n = wn * 32 + nt * 8 + g;
    dst[i] = f2tf32(W[k * D + n]);
}

// ---------------------------------------------------------------------------
// Per-block dtype detect: int64 little-endian values < 2^32 -> odd 32-bit
// words all zero over 128 samples.
// ---------------------------------------------------------------------------
__device__ __forceinline__ int detect_is64(const unsigned* p, int* s_flag) {
    if (threadIdx.x == 0) *s_flag = 0;
    __syncthreads();
    if (threadIdx.x < 64) {
        unsigned nz = p[2 * threadIdx.x + 1] | p[2 * threadIdx.x + 129];
        if (nz) atomicOr(s_flag, 1);
    }
    __syncthreads();
    return *s_flag ? 0 : 1;
}

// Parse edges (either dtype), count degrees.
__global__ void k_prep(const void* p, int E) {
    __shared__ int s_flag;
    int is64 = detect_is64((const unsigned*)p, &s_flag);
    int e = blockIdx.x * blockDim.x + threadIdx.x;
    if (e >= E) return;
    int r, c;
    if (is64) {
        const long long* q = (const long long*)p;
        r = (int)q[e];
        c = (int)q[(long long)E + e];
    } else {
        const int* q = (const int*)p;
        r = q[e];
        c = q[E + e];
    }
    atomicAdd(&g_deg[r], 1);
    atomicAdd(&g_cnt[c], 1);
}

// ---------------------------------------------------------------------------
// Block 0 (1024 thr): exclusive scan g_cnt -> g_start (shfl warp-scan),
// zero cursors, dis = rsqrt(deg+1), re-zero deg.
// Blocks 1..32: pack W1/W2 (rides free while block 0 scans).
// ---------------------------------------------------------------------------
__global__ void k_scan_dis(int N, int E,
                           const float* __restrict__ W1, const float* __restrict__ W2) {
    if (blockIdx.x > 0) {
        int i = (blockIdx.x - 1) * 1024 + threadIdx.x;
        if (i < D * D) pack_w(g_w1p, W1, i);
        else           pack_w(g_w2p, W2, i - D * D);
        return;
    }

    __shared__ int warpBase[32];
    const int tid  = threadIdx.x;
    const int lane = tid & 31;
    const int wid  = tid >> 5;
    const int per  = (N + 1023) >> 10;
    const int base = tid * per;

    int s = 0;
    {
        int i = 0;
        for (; i + 4 <= per; i += 4) {
            int i0 = base + i;
            int c0 = (i0     < N) ? g_cnt[i0]     : 0;
            int c1 = (i0 + 1 < N) ? g_cnt[i0 + 1] : 0;
            int c2 = (i0 + 2 < N) ? g_cnt[i0 + 2] : 0;
            int c3 = (i0 + 3 < N) ? g_cnt[i0 + 3] : 0;
            s += (c0 + c1) + (c2 + c3);
        }
        for (; i < per; i++) {
            int i0 = base + i;
            if (i0 < N) s += g_cnt[i0];
        }
    }

    int incl = s;
    #pragma unroll
    for (int off = 1; off < 32; off <<= 1) {
        int v = __shfl_up_sync(0xffffffffu, incl, off);
        if (lane >= off) incl += v;
    }
    if (lane == 31) warpBase[wid] = incl;
    __syncthreads();
    if (wid == 0) {
        int wv = warpBase[lane];
        int wi = wv;
        #pragma unroll
        for (int off = 1; off < 32; off <<= 1) {
            int v = __shfl_up_sync(0xffffffffu, wi, off);
            if (lane >= off) wi += v;
        }
        warpBase[lane] = wi - wv;
    }
    __syncthreads();
    int run = warpBase[wid] + (incl - s);

    {
        int i = 0;
        for (; i + 4 <= per; i += 4) {
            int i0 = base + i;
            int c0 = (i0     < N) ? g_cnt[i0]     : 0;
            int c1 = (i0 + 1 < N) ? g_cnt[i0 + 1] : 0;
            int c2 = (i0 + 2 < N) ? g_cnt[i0 + 2] : 0;
            int c3 = (i0 + 3 < N) ? g_cnt[i0 + 3] : 0;
            int d0 = (i0     < N) ? g_deg[i0]     : 0;
            int d1 = (i0 + 1 < N) ? g_deg[i0 + 1] : 0;
            int d2 = (i0 + 2 < N) ? g_deg[i0 + 2] : 0;
            int d3 = (i0 + 3 < N) ? g_deg[i0 + 3] : 0;
            if (i0 < N) {
                g_start[i0] = run;  g_cnt[i0] = 0;  g_deg[i0] = 0;
                g_dis[i0] = rsqrtf((float)(d0 + 1));
            }
            if (i0 + 1 < N) {
                g_start[i0 + 1] = run + c0;  g_cnt[i0 + 1] = 0;  g_deg[i0 + 1] = 0;
                g_dis[i0 + 1] = rsqrtf((float)(d1 + 1));
            }
            if (i0 + 2 < N) {
                g_start[i0 + 2] = run + c0 + c1;  g_cnt[i0 + 2] = 0;  g_deg[i0 + 2] = 0;
                g_dis[i0 + 2] = rsqrtf((float)(d2 + 1));
            }
            if (i0 + 3 < N) {
                g_start[i0 + 3] = run + c0 + c1 + c2;  g_cnt[i0 + 3] = 0;  g_deg[i0 + 3] = 0;
                g_dis[i0 + 3] = rsqrtf((float)(d3 + 1));
            }
            run += (c0 + c1) + (c2 + c3);
        }
        for (; i < per; i++) {
            int i0 = base + i;
            if (i0 < N) {
                int c = g_cnt[i0];
                g_start[i0] = run;  run += c;
                g_cnt[i0] = 0;
                g_dis[i0] = rsqrtf((float)(g_deg[i0] + 1));
                g_deg[i0] = 0;
            }
        }
    }
    if (tid == 0) g_start[N] = E;
}

// ---------------------------------------------------------------------------
// FUSED: blocks [0, gemmBlocks) run GEMM-1 (tf32, dis[row]*(x@W1) -> g_th);
//        blocks [gemmBlocks, ...) scatter edge src ids into the adjacency.
// GEMM epilogue scales by dis[row] so the aggregation needs no edge weights:
//   out[c] = dis[c] * (sum_e t'[src_e] + t'[c]) + bias,  t' = dis*(A@W).
// ---------------------------------------------------------------------------
__global__ void __launch_bounds__(256, 3)
k_gemm_scatter(const float* __restrict__ A, const unsigned* __restrict__ Wp,
               __half* __restrict__ C, int N,
               const void* p, int E, int gemmBlocks) {
    __shared__ unsigned As[64][36];

    if (blockIdx.x >= gemmBlocks) {
        // ---------------- scatter branch ----------------
        int is64 = detect_is64((const unsigned*)p, (int*)&As[0][0]);
        int e = (blockIdx.x - gemmBlocks) * blockDim.x + threadIdx.x;
        if (e >= E) return;
        int r, c;
        if (is64) {
            const long long* q = (const long long*)p;
            r = (int)q[e];
            c = (int)q[(long long)E + e];
        } else {
            const int* q = (const int*)p;
            r = q[e];
            c = q[E + e];
        }
        int pos = g_start[c] + atomicAdd(&g_cnt[c], 1);
        g_adjs[pos] = r;
        return;
    }

    // ---------------- GEMM branch ----------------
    const int tid  = threadIdx.x;
    const int wid  = tid >> 5;
    const int lane = tid & 31;
    const int g    = lane >> 2;
    const int t    = lane & 3;
    const int wm   = wid >> 2;
    const int wn   = wid & 3;
    const int row0 = blockIdx.x * 64;

    float acc[2][4][4];
    #pragma unroll
    for (int mt = 0; mt < 2; mt++)
        #pragma unroll
        for (int nt = 0; nt < 4; nt++)
            #pragma unroll
            for (int c = 0; c < 4; c++) acc[mt][nt][c] = 0.f;

    for (int kk4 = 0; kk4 < 4; kk4++) {
        const int kk = kk4 * 32;
        #pragma unroll
        for (int it = 0; it < 2; it++) {
            int idx = tid + it * 256;
            int m  = idx >> 3;
            int k4 = idx & 7;
            float4 v = make_float4(0.f, 0.f, 0.f, 0.f);
            int gr = row0 + m;
            if (gr < N) v = *(const float4*)(A + (long)gr * D + kk + k4 * 4);
            As[m][k4 * 4 + 0] = f2tf32(v.x);
            As[m][k4 * 4 + 1] = f2tf32(v.y);
            As[m][k4 * 4 + 2] = f2tf32(v.z);
            As[m][k4 * 4 + 3] = f2tf32(v.w);
        }
        __syncthreads();

        const unsigned* wsl = Wp + ((kk4 * 4 + wn) * 4) * 256 + lane * 4;
        #pragma unroll
        for (int ks = 0; ks < 4; ks++) {
            uint4 u0 = __ldg((const uint4*)(wsl + ks * 256));
            uint4 u1 = __ldg((const uint4*)(wsl + ks * 256 + 128));
            unsigned bf[4][2] = {{u0.x, u0.y}, {u0.z, u0.w},
                                 {u1.x, u1.y}, {u1.z, u1.w}};
            #pragma unroll
            for (int mt = 0; mt < 2; mt++) {
                int mb = wm * 32 + mt * 16;
                unsigned a0 = As[mb + g    ][ks * 8 + t    ];
                unsigned a1 = As[mb + g + 8][ks * 8 + t    ];
                unsigned a2 = As[mb + g    ][ks * 8 + t + 4];
                unsigned a3 = As[mb + g + 8][ks * 8 + t + 4];
                #pragma unroll
                for (int nt = 0; nt < 4; nt++) {
                    asm volatile(
                        "mma.sync.aligned.m16n8k8.row.col.f32.tf32.tf32.f32 "
                        "{%0,%1,%2,%3}, {%4,%5,%6,%7}, {%8,%9}, {%0,%1,%2,%3};"
                        : "+f"(acc[mt][nt][0]), "+f"(acc[mt][nt][1]),
                          "+f"(acc[mt][nt][2]), "+f"(acc[mt][nt][3])
                        : "r"(a0), "r"(a1), "r"(a2), "r"(a3),
                          "r"(bf[nt][0]), "r"(bf[nt][1]));
                }
            }
        }
        __syncthreads();
    }

    #pragma unroll
    for (int mt = 0; mt < 2; mt++) {
        int r0 = row0 + wm * 32 + mt * 16 + g;
        int r1 = r0 + 8;
        float d0 = (r0 < N) ? g_dis[r0] : 0.f;
        float d1 = (r1 < N) ? g_dis[r1] : 0.f;
        #pragma unroll
        for (int nt = 0; nt < 4; nt++) {
            int n = wn * 32 + nt * 8 + 2 * t;
            if (r0 < N)
                *(__half2*)(C + (long)r0 * D + n) =
                    __floats2half2_rn(d0 * acc[mt][nt][0], d0 * acc[mt][nt][1]);
            if (r1 < N)
                *(__half2*)(C + (long)r1 * D + n) =
                    __floats2half2_rn(d1 * acc[mt][nt][2], d1 * acc[mt][nt][3]);
        }
    }
}

// Standalone GEMM (layer 2), identical math, dis-scaled fp16 output.
__global__ void __launch_bounds__(256, 3)
k_gemm_tf32(const float* __restrict__ A, const unsigned* __restrict__ Wp,
            __half* __restrict__ C, int N) {
    __shared__ unsigned As[64][36];

    const int tid  = threadIdx.x;
    const int wid  = tid >> 5;
    const int lane = tid & 31;
    const int g    = lane >> 2;
    const int t    = lane & 3;
    const int wm   = wid >> 2;
    const int wn   = wid & 3;
    const int row0 = blockIdx.x * 64;

    float acc[2][4][4];
    #pragma unroll
    for (int mt = 0; mt < 2; mt++)
        #pragma unroll
        for (int nt = 0; nt < 4; nt++)
            #pragma unroll
            for (int c = 0; c < 4; c++) acc[mt][nt][c] = 0.f;

    for (int kk4 = 0; kk4 < 4; kk4++) {
        const int kk = kk4 * 32;
        #pragma unroll
        for (int it = 0; it < 2; it++) {
            int idx = tid + it * 256;
            int m  = idx >> 3;
            int k4 = idx & 7;
            float4 v = make_float4(0.f, 0.f, 0.f, 0.f);
            int gr = row0 + m;
            if (gr < N) v = *(const float4*)(A + (long)gr * D + kk + k4 * 4);
            As[m][k4 * 4 + 0] = f2tf32(v.x);
            As[m][k4 * 4 + 1] = f2tf32(v.y);
            As[m][k4 * 4 + 2] = f2tf32(v.z);
            As[m][k4 * 4 + 3] = f2tf32(v.w);
        }
        __syncthreads();

        const unsigned* wsl = Wp + ((kk4 * 4 + wn) * 4) * 256 + lane * 4;
        #pragma unroll
        for (int ks = 0; ks < 4; ks++) {
            uint4 u0 = __ldg((const uint4*)(wsl + ks * 256));
            uint4 u1 = __ldg((const uint4*)(wsl + ks * 256 + 128));
            unsigned bf[4][2] = {{u0.x, u0.y}, {u0.z, u0.w},
                                 {u1.x, u1.y}, {u1.z, u1.w}};
            #pragma unroll
            for (int mt = 0; mt < 2; mt++) {
                int mb = wm * 32 + mt * 16;
                unsigned a0 = As[mb + g    ][ks * 8 + t    ];
                unsigned a1 = As[mb + g + 8][ks * 8 + t    ];
                unsigned a2 = As[mb + g    ][ks * 8 + t + 4];
                unsigned a3 = As[mb + g + 8][ks * 8 + t + 4];
                #pragma unroll
                for (int nt = 0; nt < 4; nt++) {
                    asm volatile(
                        "mma.sync.aligned.m16n8k8.row.col.f32.tf32.tf32.f32 "
                        "{%0,%1,%2,%3}, {%4,%5,%6,%7}, {%8,%9}, {%0,%1,%2,%3};"
                        : "+f"(acc[mt][nt][0]), "+f"(acc[mt][nt][1]),
                          "+f"(acc[mt][nt][2]), "+f"(acc[mt][nt][3])
                        : "r"(a0), "r"(a1), "r"(a2), "r"(a3),
                          "r"(bf[nt][0]), "r"(bf[nt][1]));
                }
            }
        }
        __syncthreads();
    }

    #pragma unroll
    for (int mt = 0; mt < 2; mt++) {
        int r0 = row0 + wm * 32 + mt * 16 + g;
        int r1 = r0 + 8;
        float d0 = (r0 < N) ? g_dis[r0] : 0.f;
        float d1 = (r1 < N) ? g_dis[r1] : 0.f;
        #pragma unroll
        for (int nt = 0; nt < 4; nt++) {
            int n = wn * 32 + nt * 8 + 2 * t;
            if (r0 < N)
                *(__half2*)(C + (long)r0 * D + n) =
                    __floats2half2_rn(d0 * acc[mt][nt][0], d0 * acc[mt][nt][1]);
            if (r1 < N)
                *(__half2*)(C + (long)r1 * D + n) =
                    __floats2half2_rn(d1 * acc[mt][nt][2], d1 * acc[mt][nt][3]);
        }
    }
}

// ---------------------------------------------------------------------------
// Aggregation: pure fp16 sum (weights folded into t'), one warp per dst node.
// 4 edges/iter: int4 adjacency (4 srcs/load), pairwise fp16 hadd2 then fp32
// accumulate. out = dis[n]*(sum + t'[n]) + bias, optional ReLU.
// ---------------------------------------------------------------------------
template <bool RELU, bool CLEAN>
__global__ void __launch_bounds__(256)
k_agg(const uint2* __restrict__ src, const float4* __restrict__ bias4,
      float4* __restrict__ dst, int N) {
    if (CLEAN) {
        int idx = blockIdx.x * blockDim.x + threadIdx.x;
        if (idx < MAXN) g_cnt[idx] = 0;   // restore invariant
    }
    int w = (blockIdx.x * blockDim.x + threadIdx.x) >> 5;
    if (w >= N) return;
    const int lane = threadIdx.x & 31;
    int i = g_start[w];
    const int end = g_start[w + 1];

    float4 a0 = make_float4(0.f, 0.f, 0.f, 0.f);
    float4 a1 = make_float4(0.f, 0.f, 0.f, 0.f);

    // Peel to 16B-aligned index for int4 adjacency loads.
    while ((i & 3) && i < end) {
        int s = __ldg(&g_adjs[i]);
        uint2 p = __ldg(&src[(long)s * 32 + lane]);
        float2 fa = __half22float2(*(__half2*)&p.x);
        float2 fb = __half22float2(*(__half2*)&p.y);
        a0.x += fa.x; a0.y += fa.y; a0.z += fb.x; a0.w += fb.y;
        i++;
    }
    for (; i + 4 <= end; i += 4) {
        int4 e = __ldg((const int4*)&g_adjs[i]);
        uint2 p0 = __ldg(&src[(long)e.x * 32 + lane]);
        uint2 p1 = __ldg(&src[(long)e.y * 32 + lane]);
        uint2 p2 = __ldg(&src[(long)e.z * 32 + lane]);
        uint2 p3 = __ldg(&src[(long)e.w * 32 + lane]);
        // Pairwise fp16 adds (error ~eps per element, random-sign across pairs)
        __half2 q0a = __hadd2(*(__half2*)&p0.x, *(__half2*)&p1.x);
        __half2 q0b = __hadd2(*(__half2*)&p0.y, *(__half2*)&p1.y);
        __half2 q1a = __hadd2(*(__half2*)&p2.x, *(__half2*)&p3.x);
        __half2 q1b = __hadd2(*(__half2*)&p2.y, *(__half2*)&p3.y);
        float2 f;
        f = __half22float2(q0a); a0.x += f.x; a0.y += f.y;
        f = __half22float2(q0b); a0.z += f.x; a0.w += f.y;
        f = __half22float2(q1a); a1.x += f.x; a1.y += f.y;
        f = __half22float2(q1b); a1.z += f.x; a1.w += f.y;
    }
    for (; i < end; i++) {
        int s = __ldg(&g_adjs[i]);
        uint2 p = __ldg(&src[(long)s * 32 + lane]);
        float2 fa = __half22float2(*(__half2*)&p.x);
        float2 fb = __half22float2(*(__half2*)&p.y);
        a0.x += fa.x; a0.y += fa.y; a0.z += fb.x; a0.w += fb.y;
    }

    // Self term t'[w] (already dis-scaled), then scale the whole sum by dis.
    float di = g_dis[w];
    uint2 ps = __ldg(&src[(long)w * 32 + lane]);
    float2 s0 = __half22float2(*(__half2*)&ps.x);
    float2 s1 = __half22float2(*(__half2*)&ps.y);
    float4 bv = __ldg(&bias4[lane]);
    float4 o;
    o.x = di * (a0.x + a1.x + s0.x) + bv.x;
    o.y = di * (a0.y + a1.y + s0.y) + bv.y;
    o.z = di * (a0.z + a1.z + s1.x) + bv.z;
    o.w = di * (a0.w + a1.w + s1.y) + bv.w;
    if (RELU) {
        o.x = fmaxf(o.x, 0.f); o.y = fmaxf(o.y, 0.f);
        o.z = fmaxf(o.z, 0.f); o.w = fmaxf(o.w, 0.f);
    }
    dst[(long)w * DV + lane] = o;
}

extern "C" void kernel_launch(void* const* d_in, const int* in_sizes, int n_in,
                              void* d_out, int out_size) {
    const float* x  = (const float*)d_in[0];
    const void*  ei = d_in[1];
    const float* W1 = (const float*)d_in[2];
    const float* b1 = (const float*)d_in[3];
    const float* W2 = (const float*)d_in[4];
    const float* b2 = (const float*)d_in[5];
    float* out = (float*)d_out;

    const int N = in_sizes[0] / D;
    const int E = in_sizes[1] / 2;

    __half*   th_ptr = nullptr;
    float*    h_ptr  = nullptr;
    unsigned* w1p    = nullptr;
    unsigned* w2p    = nullptr;
    cudaGetSymbolAddress((void**)&th_ptr, g_th);
    cudaGetSymbolAddress((void**)&h_ptr,  g_h);
    cudaGetSymbolAddress((void**)&w1p,    g_w1p);
    cudaGetSymbolAddress((void**)&w2p,    g_w2p);

    const int T = 256;
    const int eGrid    = (E + T - 1) / T;
    const int aggGrid  = (N * 32 + T - 1) / T;
    const int gemmGrid = (N + 63) / 64;

    // Norm factorization: GEMM epilogues emit t' = dis[row]*(A@W) in fp16,
    // so aggregation is an unweighted fp16 sum; dis[dst]+bias+ReLU in agg.
    k_prep<<<eGrid, T>>>(ei, E);                                          // 1
    k_scan_dis<<<33, 1024>>>(N, E, W1, W2);                               // 2
    k_gemm_scatter<<<gemmGrid + eGrid, T>>>(x, w1p, th_ptr, N,            // 3
                                            ei, E, gemmGrid);
    k_agg<true, false><<<aggGrid, T>>>((const uint2*)th_ptr,              // 4
                                       (const float4*)b1, (float4*)h_ptr, N);
    k_gemm_tf32<<<gemmGrid, T>>>(h_ptr, w2p, th_ptr, N);                  // 5
    k_agg<false, true><<<aggGrid, T>>>((const uint2*)th_ptr,              // 6
                                       (const float4*)b2, (float4*)out, N);
}

// round 14
// speedup vs baseline: 1.3113x; 1.0089x over previous
#include <cuda_runtime.h>
#include <cuda_fp16.h>
#include <stdint.h>

#define D 128
#define DV 32
#define MAXN 50048
#define MAXE 1600000

// Zero-initialized at module load. Invariant: g_deg, g_cnt, g_done are zero at
// entry to kernel_launch and restored to zero before it finishes
// (prep_scan zeroes deg + done; the final k_agg zeroes cnt).
__device__ int      g_deg[MAXN];
__device__ int      g_cnt[MAXN];
__device__ int      g_done;
__device__ int      g_adjs[MAXE];       // dst-sorted src ids (weights folded into t')
__device__ int      g_start[MAXN + 1];  // CSR offsets by dst
__device__ float    g_dis[MAXN];
__device__ __half   g_th[MAXN * D];     // dis[row] * (A@W) output, fp16
__device__ float    g_h[MAXN * D];      // hidden after layer 1 (fp32)
__device__ unsigned g_w1p[D * D];       // W1, tf32 bits, lane-major fragment pack
__device__ unsigned g_w2p[D * D];       // W2, tf32 bits, lane-major fragment pack

__device__ __forceinline__ unsigned f2tf32(float f) {
    unsigned u;
    asm("cvt.rna.tf32.f32 %0, %1;" : "=r"(u) : "f"(f));
    return u;
}

// Lane-major fragment pack (see consumer in the GEMM):
//   word i = (((kk4*4 + wn)*4 + ks)*2 + jj)*128 + lane*4 + c
__device__ __forceinline__ void pack_w(unsigned* dst, const float* __restrict__ W, int i) {
    int c    = i & 3;
    int lane = (i >> 2) & 31;
    int jj   = (i >> 7) & 1;
    int ks   = (i >> 8) & 3;
    int wn   = (i >> 10) & 3;
    int kk4  = i >> 12;
    int j  = jj * 4 + c;
    int nt = j >> 1;
    int b  = j & 1;
    int t  = lane & 3;
    int g  = lane >> 2;
    int k = kk4 * 32 + ks * 8 + t + b * 4;
    int n = wn * 32 + nt * 8 + g;
    dst[i] = f2tf32(W[k * D + n]);
}

// ---------------------------------------------------------------------------
// Per-block dtype detect: int64 little-endian values < 2^32 -> odd 32-bit
// words all zero over 128 samples.
// ---------------------------------------------------------------------------
__device__ __forceinline__ int detect_is64(const unsigned* p, int* s_flag) {
    if (threadIdx.x == 0) *s_flag = 0;
    __syncthreads();
    if (threadIdx.x < 64) {
        unsigned nz = p[2 * threadIdx.x + 1] | p[2 * threadIdx.x + 129];
        if (nz) atomicOr(s_flag, 1);
    }
    __syncthreads();
    return *s_flag ? 0 : 1;
}

// ---------------------------------------------------------------------------
// FUSED prep + scan (last-block-done): every block parses its edge slice and
// counts degrees; first 128 blocks also pack W1/W2. The LAST block to finish
// performs the exclusive scan (shfl warp-scan over its 256 threads), computes
// dis = rsqrt(deg+1), zeroes deg, and resets g_done (replay-safe).
// ---------------------------------------------------------------------------
__global__ void k_prep_scan(const void* p, int E, int N,
                            const float* __restrict__ W1, const float* __restrict__ W2) {
    __shared__ int s_flag;
    __shared__ int s_last;
    int is64 = detect_is64((const unsigned*)p, &s_flag);
    int gt = blockIdx.x * blockDim.x + threadIdx.x;

    if (gt < D * D)          pack_w(g_w1p, W1, gt);
    else if (gt < 2 * D * D) pack_w(g_w2p, W2, gt - D * D);

    if (gt < E) {
        int r, c;
        if (is64) {
            const long long* q = (const long long*)p;
            r = (int)q[gt];
            c = (int)q[(long long)E + gt];
        } else {
            const int* q = (const int*)p;
            r = q[gt];
            c = q[E + gt];
        }
        atomicAdd(&g_deg[r], 1);
        atomicAdd(&g_cnt[c], 1);
    }

    // Last-block election.
    __syncthreads();
    if (threadIdx.x == 0) {
        __threadfence();
        s_last = (atomicAdd(&g_done, 1) == (int)gridDim.x - 1);
    }
    __syncthreads();
    if (!s_last) return;
    __threadfence();

    // ---- scan (256 threads) ----
    __shared__ int warpBase[8];
    const int tid  = threadIdx.x;
    const int lane = tid & 31;
    const int wid  = tid >> 5;
    const int per  = (N + 255) >> 8;
    const int base = tid * per;

    int s = 0;
    {
        int i = 0;
        for (; i + 4 <= per; i += 4) {
            int i0 = base + i;
            int c0 = (i0     < N) ? g_cnt[i0]     : 0;
            int c1 = (i0 + 1 < N) ? g_cnt[i0 + 1] : 0;
            int c2 = (i0 + 2 < N) ? g_cnt[i0 + 2] : 0;
            int c3 = (i0 + 3 < N) ? g_cnt[i0 + 3] : 0;
            s += (c0 + c1) + (c2 + c3);
        }
        for (; i < per; i++) {
            int i0 = base + i;
            if (i0 < N) s += g_cnt[i0];
        }
    }

    int incl = s;
    #pragma unroll
    for (int off = 1; off < 32; off <<= 1) {
        int v = __shfl_up_sync(0xffffffffu, incl, off);
        if (lane >= off) incl += v;
    }
    if (lane == 31) warpBase[wid] = incl;
    __syncthreads();
    if (wid == 0 && lane < 8) {
        int wv = warpBase[lane];
        int wi = wv;
        #pragma unroll
        for (int off = 1; off < 8; off <<= 1) {
            int v = __shfl_up_sync(0xffu, wi, off);
            if (lane >= off) wi += v;
        }
        warpBase[lane] = wi - wv;
    }
    __syncthreads();
    int run = warpBase[wid] + (incl - s);

    {
        int i = 0;
        for (; i + 4 <= per; i += 4) {
            int i0 = base + i;
            int c0 = (i0     < N) ? g_cnt[i0]     : 0;
            int c1 = (i0 + 1 < N) ? g_cnt[i0 + 1] : 0;
            int c2 = (i0 + 2 < N) ? g_cnt[i0 + 2] : 0;
            int c3 = (i0 + 3 < N) ? g_cnt[i0 + 3] : 0;
            int d0 = (i0     < N) ? g_deg[i0]     : 0;
            int d1 = (i0 + 1 < N) ? g_deg[i0 + 1] : 0;
            int d2 = (i0 + 2 < N) ? g_deg[i0 + 2] : 0;
            int d3 = (i0 + 3 < N) ? g_deg[i0 + 3] : 0;
            if (i0 < N) {
                g_start[i0] = run;  g_cnt[i0] = 0;  g_deg[i0] = 0;
                g_dis[i0] = rsqrtf((float)(d0 + 1));
            }
            if (i0 + 1 < N) {
                g_start[i0 + 1] = run + c0;  g_cnt[i0 + 1] = 0;  g_deg[i0 + 1] = 0;
                g_dis[i0 + 1] = rsqrtf((float)(d1 + 1));
            }
            if (i0 + 2 < N) {
                g_start[i0 + 2] = run + c0 + c1;  g_cnt[i0 + 2] = 0;  g_deg[i0 + 2] = 0;
                g_dis[i0 + 2] = rsqrtf((float)(d2 + 1));
            }
            if (i0 + 3 < N) {
                g_start[i0 + 3] = run + c0 + c1 + c2;  g_cnt[i0 + 3] = 0;  g_deg[i0 + 3] = 0;
                g_dis[i0 + 3] = rsqrtf((float)(d3 + 1));
            }
            run += (c0 + c1) + (c2 + c3);
        }
        for (; i < per; i++) {
            int i0 = base + i;
            if (i0 < N) {
                int c = g_cnt[i0];
                g_start[i0] = run;  run += c;
                g_cnt[i0] = 0;
                g_dis[i0] = rsqrtf((float)(g_deg[i0] + 1));
                g_deg[i0] = 0;
            }
        }
    }
    if (tid == 0) {
        g_start[N] = E;
        g_done = 0;   // restore invariant for graph replay
    }
}

// ---------------------------------------------------------------------------
// FUSED: blocks [0, gemmBlocks) run GEMM-1 (tf32, dis[row]*(x@W1) -> g_th);
//        blocks [gemmBlocks, ...) scatter edge src ids into the adjacency.
// ---------------------------------------------------------------------------
__global__ void __launch_bounds__(256, 3)
k_gemm_scatter(const float* __restrict__ A, const unsigned* __restrict__ Wp,
               __half* __restrict__ C, int N,
               const void* p, int E, int gemmBlocks) {
    __shared__ unsigned As[64][36];

    if (blockIdx.x >= gemmBlocks) {
        // ---------------- scatter branch ----------------
        int is64 = detect_is64((const unsigned*)p, (int*)&As[0][0]);
        int e = (blockIdx.x - gemmBlocks) * blockDim.x + threadIdx.x;
        if (e >= E) return;
        int r, c;
        if (is64) {
            const long long* q = (const long long*)p;
            r = (int)q[e];
            c = (int)q[(long long)E + e];
        } else {
            const int* q = (const int*)p;
            r = q[e];
            c = q[E + e];
        }
        int pos = g_start[c] + atomicAdd(&g_cnt[c], 1);
        g_adjs[pos] = r;
        return;
    }

    // ---------------- GEMM branch ----------------
    const int tid  = threadIdx.x;
    const int wid  = tid >> 5;
    const int lane = tid & 31;
    const int g    = lane >> 2;
    const int t    = lane & 3;
    const int wm   = wid >> 2;
    const int wn   = wid & 3;
    const int row0 = blockIdx.x * 64;

    float acc[2][4][4];
    #pragma unroll
    for (int mt = 0; mt < 2; mt++)
        #pragma unroll
        for (int nt = 0; nt < 4; nt++)
            #pragma unroll
            for (int c = 0; c < 4; c++) acc[mt][nt][c] = 0.f;

    for (int kk4 = 0; kk4 < 4; kk4++) {
        const int kk = kk4 * 32;
        #pragma unroll
        for (int it = 0; it < 2; it++) {
            int idx = tid + it * 256;
            int m  = idx >> 3;
            int k4 = idx & 7;
            float4 v = make_float4(0.f, 0.f, 0.f, 0.f);
            int gr = row0 + m;
            if (gr < N) v = *(const float4*)(A + (long)gr * D + kk + k4 * 4);
            As[m][k4 * 4 + 0] = f2tf32(v.x);
            As[m][k4 * 4 + 1] = f2tf32(v.y);
            As[m][k4 * 4 + 2] = f2tf32(v.z);
            As[m][k4 * 4 + 3] = f2tf32(v.w);
        }
        __syncthreads();

        const unsigned* wsl = Wp + ((kk4 * 4 + wn) * 4) * 256 + lane * 4;
        #pragma unroll
        for (int ks = 0; ks < 4; ks++) {
            uint4 u0 = __ldg((const uint4*)(wsl + ks * 256));
            uint4 u1 = __ldg((const uint4*)(wsl + ks * 256 + 128));
            unsigned bf[4][2] = {{u0.x, u0.y}, {u0.z, u0.w},
                                 {u1.x, u1.y}, {u1.z, u1.w}};
            #pragma unroll
            for (int mt = 0; mt < 2; mt++) {
                int mb = wm * 32 + mt * 16;
                unsigned a0 = As[mb + g    ][ks * 8 + t    ];
                unsigned a1 = As[mb + g + 8][ks * 8 + t    ];
                unsigned a2 = As[mb + g    ][ks * 8 + t + 4];
                unsigned a3 = As[mb + g + 8][ks * 8 + t + 4];
                #pragma unroll
                for (int nt = 0; nt < 4; nt++) {
                    asm volatile(
                        "mma.sync.aligned.m16n8k8.row.col.f32.tf32.tf32.f32 "
                        "{%0,%1,%2,%3}, {%4,%5,%6,%7}, {%8,%9}, {%0,%1,%2,%3};"
                        : "+f"(acc[mt][nt][0]), "+f"(acc[mt][nt][1]),
                          "+f"(acc[mt][nt][2]), "+f"(acc[mt][nt][3])
                        : "r"(a0), "r"(a1), "r"(a2), "r"(a3),
                          "r"(bf[nt][0]), "r"(bf[nt][1]));
                }
            }
        }
        __syncthreads();
    }

    #pragma unroll
    for (int mt = 0; mt < 2; mt++) {
        int r0 = row0 + wm * 32 + mt * 16 + g;
        int r1 = r0 + 8;
        float d0 = (r0 < N) ? g_dis[r0] : 0.f;
        float d1 = (r1 < N) ? g_dis[r1] : 0.f;
        #pragma unroll
        for (int nt = 0; nt < 4; nt++) {
            int n = wn * 32 + nt * 8 + 2 * t;
            if (r0 < N)
                *(__half2*)(C + (long)r0 * D + n) =
                    __floats2half2_rn(d0 * acc[mt][nt][0], d0 * acc[mt][nt][1]);
            if (r1 < N)
                *(__half2*)(C + (long)r1 * D + n) =
                    __floats2half2_rn(d1 * acc[mt][nt][2], d1 * acc[mt][nt][3]);
        }
    }
}

// Standalone GEMM (layer 2), identical math, dis-scaled fp16 output.
__global__ void __launch_bounds__(256, 3)
k_gemm_tf32(const float* __restrict__ A, const unsigned* __restrict__ Wp,
            __half* __restrict__ C, int N) {
    __shared__ unsigned As[64][36];

    const int tid  = threadIdx.x;
    const int wid  = tid >> 5;
    const int lane = tid & 31;
    const int g    = lane >> 2;
    const int t    = lane & 3;
    const int wm   = wid >> 2;
    const int wn   = wid & 3;
    const int row0 = blockIdx.x * 64;

    float acc[2][4][4];
    #pragma unroll
    for (int mt = 0; mt < 2; mt++)
        #pragma unroll
        for (int nt = 0; nt < 4; nt++)
            #pragma unroll
            for (int c = 0; c < 4; c++) acc[mt][nt][c] = 0.f;

    for (int kk4 = 0; kk4 < 4; kk4++) {
        const int kk = kk4 * 32;
        #pragma unroll
        for (int it = 0; it < 2; it++) {
            int idx = tid + it * 256;
            int m  = idx >> 3;
            int k4 = idx & 7;
            float4 v = make_float4(0.f, 0.f, 0.f, 0.f);
            int gr = row0 + m;
            if (gr < N) v = *(const float4*)(A + (long)gr * D + kk + k4 * 4);
            As[m][k4 * 4 + 0] = f2tf32(v.x);
            As[m][k4 * 4 + 1] = f2tf32(v.y);
            As[m][k4 * 4 + 2] = f2tf32(v.z);
            As[m][k4 * 4 + 3] = f2tf32(v.w);
        }
        __syncthreads();

        const unsigned* wsl = Wp + ((kk4 * 4 + wn) * 4) * 256 + lane * 4;
        #pragma unroll
        for (int ks = 0; ks < 4; ks++) {
            uint4 u0 = __ldg((const uint4*)(wsl + ks * 256));
            uint4 u1 = __ldg((const uint4*)(wsl + ks * 256 + 128));
            unsigned bf[4][2] = {{u0.x, u0.y}, {u0.z, u0.w},
                                 {u1.x, u1.y}, {u1.z, u1.w}};
            #pragma unroll
            for (int mt = 0; mt < 2; mt++) {
                int mb = wm * 32 + mt * 16;
                unsigned a0 = As[mb + g    ][ks * 8 + t    ];
                unsigned a1 = As[mb + g + 8][ks * 8 + t    ];
                unsigned a2 = As[mb + g    ][ks * 8 + t + 4];
                unsigned a3 = As[mb + g + 8][ks * 8 + t + 4];
                #pragma unroll
                for (int nt = 0; nt < 4; nt++) {
                    asm volatile(
                        "mma.sync.aligned.m16n8k8.row.col.f32.tf32.tf32.f32 "
                        "{%0,%1,%2,%3}, {%4,%5,%6,%7}, {%8,%9}, {%0,%1,%2,%3};"
                        : "+f"(acc[mt][nt][0]), "+f"(acc[mt][nt][1]),
                          "+f"(acc[mt][nt][2]), "+f"(acc[mt][nt][3])
                        : "r"(a0), "r"(a1), "r"(a2), "r"(a3),
                          "r"(bf[nt][0]), "r"(bf[nt][1]));
                }
            }
        }
        __syncthreads();
    }

    #pragma unroll
    for (int mt = 0; mt < 2; mt++) {
        int r0 = row0 + wm * 32 + mt * 16 + g;
        int r1 = r0 + 8;
        float d0 = (r0 < N) ? g_dis[r0] : 0.f;
        float d1 = (r1 < N) ? g_dis[r1] : 0.f;
        #pragma unroll
        for (int nt = 0; nt < 4; nt++) {
            int n = wn * 32 + nt * 8 + 2 * t;
            if (r0 < N)
                *(__half2*)(C + (long)r0 * D + n) =
                    __floats2half2_rn(d0 * acc[mt][nt][0], d0 * acc[mt][nt][1]);
            if (r1 < N)
                *(__half2*)(C + (long)r1 * D + n) =
                    __floats2half2_rn(d1 * acc[mt][nt][2], d1 * acc[mt][nt][3]);
        }
    }
}

// ---------------------------------------------------------------------------
// Aggregation: pure fp16 sum, one warp per dst node. 4 edges/iter reduced in
// a depth-2 fp16 tree (6x hadd2), single fp32 accumulate (4 cvt + 4 fadd).
// out = dis[n]*(sum + t'[n]) + bias, optional ReLU.
// ---------------------------------------------------------------------------
template <bool RELU, bool CLEAN>
__global__ void __launch_bounds__(256)
k_agg(const uint2* __restrict__ src, const float4* __restrict__ bias4,
      float4* __restrict__ dst, int N) {
    if (CLEAN) {
        int idx = blockIdx.x * blockDim.x + threadIdx.x;
        if (idx < MAXN) g_cnt[idx] = 0;   // restore invariant
    }
    int w = (blockIdx.x * blockDim.x + threadIdx.x) >> 5;
    if (w >= N) return;
    const int lane = threadIdx.x & 31;
    int i = g_start[w];
    const int end = g_start[w + 1];

    float4 a0 = make_float4(0.f, 0.f, 0.f, 0.f);

    // Peel to 16B-aligned index for int4 adjacency loads.
    while ((i & 3) && i < end) {
        uint2 p = __ldg(&src[__ldg(&g_adjs[i]) * 32 + lane]);
        float2 fa = __half22float2(*(__half2*)&p.x);
        float2 fb = __half22float2(*(__half2*)&p.y);
        a0.x += fa.x; a0.y += fa.y; a0.z += fb.x; a0.w += fb.y;
        i++;
    }
    for (; i + 4 <= end; i += 4) {
        int4 e = __ldg((const int4*)&g_adjs[i]);
        uint2 p0 = __ldg(&src[e.x * 32 + lane]);
        uint2 p1 = __ldg(&src[e.y * 32 + lane]);
        uint2 p2 = __ldg(&src[e.z * 32 + lane]);
        uint2 p3 = __ldg(&src[e.w * 32 + lane]);
        // Depth-2 fp16 tree: 2 roundings per element, random-sign cancellation.
        __half2 q0a = __hadd2(*(__half2*)&p0.x, *(__half2*)&p1.x);
        __half2 q0b = __hadd2(*(__half2*)&p0.y, *(__half2*)&p1.y);
        __half2 q1a = __hadd2(*(__half2*)&p2.x, *(__half2*)&p3.x);
        __half2 q1b = __hadd2(*(__half2*)&p2.y, *(__half2*)&p3.y);
        __half2 ra  = __hadd2(q0a, q1a);
        __half2 rb  = __hadd2(q0b, q1b);
        float2 f;
        f = __half22float2(ra); a0.x += f.x; a0.y += f.y;
        f = __half22float2(rb); a0.z += f.x; a0.w += f.y;
    }
    for (; i < end; i++) {
        uint2 p = __ldg(&src[__ldg(&g_adjs[i]) * 32 + lane]);
        float2 fa = __half22float2(*(__half2*)&p.x);
        float2 fb = __half22float2(*(__half2*)&p.y);
        a0.x += fa.x; a0.y += fa.y; a0.z += fb.x; a0.w += fb.y;
    }

    // Self term t'[w] (already dis-scaled), then scale the whole sum by dis.
    float di = g_dis[w];
    uint2 ps = __ldg(&src[w * 32 + lane]);
    float2 s0 = __half22float2(*(__half2*)&ps.x);
    float2 s1 = __half22float2(*(__half2*)&ps.y);
    float4 bv = __ldg(&bias4[lane]);
    float4 o;
    o.x = di * (a0.x + s0.x) + bv.x;
    o.y = di * (a0.y + s0.y) + bv.y;
    o.z = di * (a0.z + s1.x) + bv.z;
    o.w = di * (a0.w + s1.y) + bv.w;
    if (RELU) {
        o.x = fmaxf(o.x, 0.f); o.y = fmaxf(o.y, 0.f);
        o.z = fmaxf(o.z, 0.f); o.w = fmaxf(o.w, 0.f);
    }
    dst[(long)w * DV + lane] = o;
}

extern "C" void kernel_launch(void* const* d_in, const int* in_sizes, int n_in,
                              void* d_out, int out_size) {
    const float* x  = (const float*)d_in[0];
    const void*  ei = d_in[1];
    const float* W1 = (const float*)d_in[2];
    const float* b1 = (const float*)d_in[3];
    const float* W2 = (const float*)d_in[4];
    const float* b2 = (const float*)d_in[5];
    float* out = (float*)d_out;

    const int N = in_sizes[0] / D;
    const int E = in_sizes[1] / 2;

    __half*   th_ptr = nullptr;
    float*    h_ptr  = nullptr;
    unsigned* w1p    = nullptr;
    unsigned* w2p    = nullptr;
    cudaGetSymbolAddress((void**)&th_ptr, g_th);
    cudaGetSymbolAddress((void**)&h_ptr,  g_h);
    cudaGetSymbolAddress((void**)&w1p,    g_w1p);
    cudaGetSymbolAddress((void**)&w2p,    g_w2p);

    const int T = 256;
    const int eGrid    = (E + T - 1) / T;
    const int aggGrid  = (N * 32 + T - 1) / T;
    const int gemmGrid = (N + 63) / 64;

    // Norm factorization: GEMM epilogues emit t' = dis[row]*(A@W) in fp16,
    // aggregation is an unweighted fp16 sum; dis[dst]+bias+ReLU in agg.
    // prep+scan fused via last-block-done; scatter fused with GEMM-1.
    k_prep_scan<<<eGrid, T>>>(ei, E, N, W1, W2);                          // 1
    k_gemm_scatter<<<gemmGrid + eGrid, T>>>(x, w1p, th_ptr, N,            // 2
                                            ei, E, gemmGrid);
    k_agg<true, false><<<aggGrid, T>>>((const uint2*)th_ptr,              // 3
                                       (const float4*)b1, (float4*)h_ptr, N);
    k_gemm_tf32<<<gemmGrid, T>>>(h_ptr, w2p, th_ptr, N);                  // 4
    k_agg<false, true><<<aggGrid, T>>>((const uint2*)th_ptr,              // 5
                                       (const float4*)b2, (float4*)out, N);
}